// round 1
// baseline (speedup 1.0000x reference)
#include <cuda_runtime.h>
#include <math.h>

// ---------------------------------------------------------------------------
// Actor_15324443312913: tree-structured actor network, all layers as grouped
// GEMMs:  C[g] = act(A[g] @ W[g] + bias[g])
//
// Layout trick: d_out's embeds region [B, 85, D] IS the activation graph.
//   nodes 0..63  : encoder outputs
//   nodes 64..79 : agg0 outputs
//   nodes 80..83 : agg1 outputs
//   node  84     : agg2 output (root, head input)
// Aggregator input "concat of 4 siblings" == 512 contiguous floats within a
// row of embeds (row stride 85*128), so every layer is a strided GEMM.
// ---------------------------------------------------------------------------

#define BATCH 4096
#define LDE   (85 * 128)   // embeds row stride

// ping-pong hidden-activation scratch: max(64*4096*128, 16*4096*512) floats
__device__ float g_h1[33554432];
__device__ float g_h2[33554432];

// ACT: 0 = none, 1 = relu, 2 = tanh
template <int BM, int BN, int BK, int TM, int TN, int ACT>
__global__ __launch_bounds__(256, 2)
void gemm_grouped(const float* __restrict__ A, long aGrp, int lda,
                  const float* __restrict__ W, long wGrp,
                  const float* __restrict__ Bias, long bGrp,
                  float* __restrict__ C, long cGrp, int ldc,
                  int M, int N, int K)
{
    __shared__ float As[BK][BM];   // A stored transposed: As[k][m]
    __shared__ float Bs[BK][BN];

    const int g  = blockIdx.z;
    const float* Ag = A    + (long)g * aGrp;
    const float* Wg = W    + (long)g * wGrp;
    const float* Bg = Bias + (long)g * bGrp;
    float*       Cg = C    + (long)g * cGrp;

    const int m0  = blockIdx.y * BM;
    const int n0  = blockIdx.x * BN;
    const int tid = threadIdx.x;          // 256 threads

    const int tcol = tid % (BN / TN);
    const int trow = tid / (BN / TN);

    float acc[TM][TN];
#pragma unroll
    for (int i = 0; i < TM; i++)
#pragma unroll
        for (int j = 0; j < TN; j++) acc[i][j] = 0.f;

    constexpr int AV = (BM * BK) / (4 * 256);   // float4 loads per thread (A)
    constexpr int BV = (BK * BN) / (4 * 256);   // float4 loads per thread (B)

    for (int k0 = 0; k0 < K; k0 += BK) {
        // ---- stage A tile (M always a multiple of BM in this net) ----
#pragma unroll
        for (int i = 0; i < AV; i++) {
            int v    = tid + i * 256;
            int arow = v / (BK / 4);
            int kq   = v % (BK / 4);
            float4 t = *reinterpret_cast<const float4*>(
                &Ag[(long)(m0 + arow) * lda + k0 + kq * 4]);
            As[kq * 4 + 0][arow] = t.x;
            As[kq * 4 + 1][arow] = t.y;
            As[kq * 4 + 2][arow] = t.z;
            As[kq * 4 + 3][arow] = t.w;
        }
        // ---- stage B tile (guard N: head output layer has N=32) ----
#pragma unroll
        for (int i = 0; i < BV; i++) {
            int v   = tid + i * 256;
            int k   = v / (BN / 4);
            int cq  = v % (BN / 4);
            int col = n0 + cq * 4;
            float4 t = make_float4(0.f, 0.f, 0.f, 0.f);
            if (col < N)
                t = *reinterpret_cast<const float4*>(&Wg[(long)(k0 + k) * N + col]);
            *reinterpret_cast<float4*>(&Bs[k][cq * 4]) = t;
        }
        __syncthreads();

#pragma unroll
        for (int k = 0; k < BK; k++) {
            float a[TM], b[TN];
#pragma unroll
            for (int i = 0; i < TM; i++) a[i] = As[k][trow * TM + i];
#pragma unroll
            for (int j = 0; j < TN; j++) b[j] = Bs[k][tcol * TN + j];
#pragma unroll
            for (int i = 0; i < TM; i++)
#pragma unroll
                for (int j = 0; j < TN; j++)
                    acc[i][j] = fmaf(a[i], b[j], acc[i][j]);
        }
        __syncthreads();
    }

    // ---- epilogue: bias + activation ----
#pragma unroll
    for (int i = 0; i < TM; i++) {
        int row = m0 + trow * TM + i;
#pragma unroll
        for (int j = 0; j < TN; j++) {
            int col = n0 + tcol * TN + j;
            if (col < N) {
                float v = acc[i][j] + Bg[col];
                if (ACT == 1) v = v > 0.f ? v : 0.f;
                if (ACT == 2) v = tanhf(v);
                Cg[(long)row * ldc + col] = v;
            }
        }
    }
}

// launch helpers -------------------------------------------------------------
template <int ACT>
static inline void run_big(const float* A, long aG, int lda,
                           const float* W, long wG,
                           const float* B, long bG,
                           float* C, long cG, int ldc,
                           int M, int N, int K, int G)
{
    dim3 grid((N + 127) / 128, M / 128, G);
    gemm_grouped<128, 128, 16, 8, 8, ACT><<<grid, 256>>>(
        A, aG, lda, W, wG, B, bG, C, cG, ldc, M, N, K);
}

template <int ACT>
static inline void run_small(const float* A, long aG, int lda,
                             const float* W, long wG,
                             const float* B, long bG,
                             float* C, long cG, int ldc,
                             int M, int N, int K, int G)
{
    dim3 grid((N + 63) / 64, M / 64, G);
    gemm_grouped<64, 64, 16, 4, 4, ACT><<<grid, 256>>>(
        A, aG, lda, W, wG, B, bG, C, cG, ldc, M, N, K);
}

extern "C" void kernel_launch(void* const* d_in, const int* in_sizes, int n_in,
                              void* d_out, int out_size)
{
    const float* state  = (const float*)d_in[0];
    const float* enc_w1 = (const float*)d_in[1];
    const float* enc_b1 = (const float*)d_in[2];
    const float* enc_wh = (const float*)d_in[3];
    const float* enc_bh = (const float*)d_in[4];
    const float* enc_wo = (const float*)d_in[5];
    const float* enc_bo = (const float*)d_in[6];
    const float* a0w1 = (const float*)d_in[7];
    const float* a0b1 = (const float*)d_in[8];
    const float* a0wh = (const float*)d_in[9];
    const float* a0bh = (const float*)d_in[10];
    const float* a0wo = (const float*)d_in[11];
    const float* a0bo = (const float*)d_in[12];
    const float* a1w1 = (const float*)d_in[13];
    const float* a1b1 = (const float*)d_in[14];
    const float* a1wh = (const float*)d_in[15];
    const float* a1bh = (const float*)d_in[16];
    const float* a1wo = (const float*)d_in[17];
    const float* a1bo = (const float*)d_in[18];
    const float* a2w1 = (const float*)d_in[19];
    const float* a2b1 = (const float*)d_in[20];
    const float* a2wh = (const float*)d_in[21];
    const float* a2bh = (const float*)d_in[22];
    const float* a2wo = (const float*)d_in[23];
    const float* a2bo = (const float*)d_in[24];
    const float* hw1  = (const float*)d_in[25];
    const float* hb1  = (const float*)d_in[26];
    const float* hwh  = (const float*)d_in[27];
    const float* hbh  = (const float*)d_in[28];
    const float* hwo  = (const float*)d_in[29];
    const float* hbo  = (const float*)d_in[30];

    float* emb    = (float*)d_out;                       // [4096, 85, 128]
    float* action = emb + (long)BATCH * 85 * 128;        // [4096, 32]

    float *h1, *h2;
    cudaGetSymbolAddress((void**)&h1, g_h1);
    cudaGetSymbolAddress((void**)&h2, g_h2);

    const int Bm = BATCH, D = 128, S = 256, CD = 512;

    // ---- encoders (G=64): state[B,256] -> 128 -> 128 -> embeds nodes 0..63
    run_big<1>(state, 0L, S,        enc_w1, (long)S * D, enc_b1, D,
               h1, (long)Bm * D, D, Bm, D, S, 64);
    run_big<1>(h1, (long)Bm * D, D, enc_wh, (long)D * D, enc_bh, D,
               h2, (long)Bm * D, D, Bm, D, D, 64);
    run_big<0>(h2, (long)Bm * D, D, enc_wo, (long)D * D, enc_bo, D,
               emb, (long)D, LDE,   Bm, D, D, 64);

    // ---- agg level 0 (G=16): in = embeds nodes 0..63 (512 contiguous/row)
    run_big<1>(emb, 512L, LDE,       a0w1, (long)CD * CD, a0b1, CD,
               h1, (long)Bm * CD, CD, Bm, CD, CD, 16);
    run_big<1>(h1, (long)Bm * CD, CD, a0wh, (long)CD * CD, a0bh, CD,
               h2, (long)Bm * CD, CD, Bm, CD, CD, 16);
    run_big<0>(h2, (long)Bm * CD, CD, a0wo, (long)CD * D,  a0bo, D,
               emb + 64 * 128, (long)D, LDE, Bm, D, CD, 16);

    // ---- agg level 1 (G=4): in = embeds nodes 64..79
    run_big<1>(emb + 64 * 128, 512L, LDE, a1w1, (long)CD * CD, a1b1, CD,
               h1, (long)Bm * CD, CD, Bm, CD, CD, 4);
    run_big<1>(h1, (long)Bm * CD, CD,     a1wh, (long)CD * CD, a1bh, CD,
               h2, (long)Bm * CD, CD, Bm, CD, CD, 4);
    run_small<0>(h2, (long)Bm * CD, CD,   a1wo, (long)CD * D,  a1bo, D,
                 emb + 80 * 128, (long)D, LDE, Bm, D, CD, 4);

    // ---- agg level 2 (G=1): in = embeds nodes 80..83
    run_small<1>(emb + 80 * 128, 0L, LDE, a2w1, 0L, a2b1, 0L,
                 h1, 0L, CD, Bm, CD, CD, 1);
    run_small<1>(h1, 0L, CD,              a2wh, 0L, a2bh, 0L,
                 h2, 0L, CD, Bm, CD, CD, 1);
    run_small<0>(h2, 0L, CD,              a2wo, 0L, a2bo, 0L,
                 emb + 84 * 128, 0L, LDE, Bm, D, CD, 1);

    // ---- head (G=1): root = embeds node 84 -> 128 -> 128 -> tanh -> 32
    run_small<1>(emb + 84 * 128, 0L, LDE, hw1, 0L, hb1, 0L,
                 h1, 0L, D, Bm, D, D, 1);
    run_small<1>(h1, 0L, D,                hwh, 0L, hbh, 0L,
                 h2, 0L, D, Bm, D, D, 1);
    run_small<2>(h2, 0L, D,                hwo, 0L, hbo, 0L,
                 action, 0L, 32, Bm, 32, D, 1);
}

// round 7
// speedup vs baseline: 2.4437x; 2.4437x over previous
#include <cuda_runtime.h>
#include <cuda_bf16.h>
#include <cstdint>
#include <math.h>

// ===========================================================================
// Actor_15324443312913 — mma.sync (HMMA) bf16 hi/lo-split grouped GEMM.
// (tcgen05 is unusable: harness ptxas targets sm_103 without the 'a' suffix.)
// All 15 layers:  C[g] = act(A[g] @ W[g] + b[g]),  fp32 in/out.
// x = hi + lo (bf16 each); A@W = hi*hi + hi*lo + lo*hi, fp32 accumulation.
// embeds buffer [B,85,128] doubles as the activation tree:
//   nodes 0..63 enc | 64..79 agg0 | 80..83 agg1 | 84 agg2/root.
// ===========================================================================

#define BATCH 4096
#define LDE   (85 * 128)

#define WT_TOTAL 16617472
__device__ __nv_bfloat16 g_whi[WT_TOTAL];
__device__ __nv_bfloat16 g_wlo[WT_TOTAL];
__device__ float g_h1[33554432];
__device__ float g_h2[33554432];

// ---------------- helpers ---------------------------------------------------
__device__ __forceinline__ uint32_t smem_u32(const void* p) {
    uint32_t a;
    asm("{ .reg .u64 t; cvta.to.shared.u64 t, %1; cvt.u32.u64 %0, t; }"
        : "=r"(a) : "l"(p));
    return a;
}
__device__ __forceinline__ void ldsm4(uint32_t* r, uint32_t addr) {
    asm volatile("ldmatrix.sync.aligned.m8n8.x4.shared.b16 {%0,%1,%2,%3}, [%4];"
                 : "=r"(r[0]), "=r"(r[1]), "=r"(r[2]), "=r"(r[3]) : "r"(addr));
}
__device__ __forceinline__ void mma_bf16(float* c, const uint32_t* a,
                                         const uint32_t* b) {
    asm volatile(
        "mma.sync.aligned.m16n8k16.row.col.f32.bf16.bf16.f32 "
        "{%0,%1,%2,%3},{%4,%5,%6,%7},{%8,%9},{%0,%1,%2,%3};"
        : "+f"(c[0]), "+f"(c[1]), "+f"(c[2]), "+f"(c[3])
        : "r"(a[0]), "r"(a[1]), "r"(a[2]), "r"(a[3]), "r"(b[0]), "r"(b[1]));
}

// ---------------- weight prep: transpose [K,N] -> [N,K] + hi/lo split ------
__global__ void prep_w(const float* __restrict__ in, __nv_bfloat16* __restrict__ hi,
                       __nv_bfloat16* __restrict__ lo, int K, int N) {
    __shared__ float t[32][33];
    const long grp = (long)K * N;
    const float* ing = in + blockIdx.z * grp;
    __nv_bfloat16* hig = hi + blockIdx.z * grp;
    __nv_bfloat16* log_ = lo + blockIdx.z * grp;
    int n0 = blockIdx.x * 32, k0 = blockIdx.y * 32;
    int tx = threadIdx.x, ty = threadIdx.y;
#pragma unroll
    for (int i = 0; i < 32; i += 8)
        t[ty + i][tx] = ing[(long)(k0 + ty + i) * N + n0 + tx];
    __syncthreads();
#pragma unroll
    for (int i = 0; i < 32; i += 8) {
        float v = t[tx][ty + i];
        __nv_bfloat16 h = __float2bfloat16(v);
        float r = v - __bfloat162float(h);
        long o = (long)(n0 + ty + i) * K + k0 + tx;
        hig[o] = h;
        log_[o] = __float2bfloat16(r);
    }
}

// ---------------- main GEMM kernel -----------------------------------------
// CTA 128 thr = 4 warps (2x2); tile M128 x N64, K-chunk 32.
// smem rows padded to 40 bf16 (80 B) -> ldmatrix conflict-free.
template <int ACT>  // 0 none, 1 relu, 2 tanh
__global__ __launch_bounds__(128, 3)
void gemm_mma(const float* __restrict__ A, long aGrp, int lda,
              const __nv_bfloat16* __restrict__ WHi,
              const __nv_bfloat16* __restrict__ WLo, long wGrp,
              const float* __restrict__ Bias, long bGrp,
              float* __restrict__ C, long cGrp, int ldc, int N, int K) {
    __shared__ __align__(16) __nv_bfloat16 sAh[128 * 40];
    __shared__ __align__(16) __nv_bfloat16 sAl[128 * 40];
    __shared__ __align__(16) __nv_bfloat16 sBh[64 * 40];
    __shared__ __align__(16) __nv_bfloat16 sBl[64 * 40];
    __shared__ float sBias[64];

    const int tid = threadIdx.x, w = tid >> 5, L = tid & 31;
    const int wr = w >> 1, wc = w & 1;
    const int g = blockIdx.z;
    const int m0 = blockIdx.y * 128, n0 = blockIdx.x * 64;

    const float* Ag = A + (long)g * aGrp + (long)m0 * lda;
    const __nv_bfloat16* WHg = WHi + (long)g * wGrp + (long)n0 * K;
    const __nv_bfloat16* WLg = WLo + (long)g * wGrp + (long)n0 * K;

    if (tid < 64) {
        int c = n0 + tid;
        sBias[tid] = (c < N) ? Bias[(long)g * bGrp + c] : 0.f;
    }

    float acc[64];
#pragma unroll
    for (int i = 0; i < 64; i++) acc[i] = 0.f;

    const uint32_t aBh = smem_u32(sAh), aBl = smem_u32(sAl);
    const uint32_t bBh = smem_u32(sBh), bBl = smem_u32(sBl);
    // per-lane ldmatrix byte offsets (A: 16x16 tiles; B: two 16x8 tiles per x4)
    const uint32_t a_off =
        (uint32_t)((wr * 64 + (L & 7) + ((L >> 3) & 1) * 8) * 80 +
                   ((L >> 4) & 1) * 16);
    const uint32_t b_off =
        (uint32_t)((wc * 32 + (L & 7) + ((L >> 4) & 1) * 8) * 80 +
                   ((L >> 3) & 1) * 16);

    const int nch = K >> 5;
    for (int ch = 0; ch < nch; ch++) {
        const int k0 = ch << 5;
        __syncthreads();  // previous chunk's smem readers done

        // ---- stage A [128 x 32] fp32 -> hi/lo bf16 ----
        const float* Ab = Ag + k0;
#pragma unroll
        for (int i = 0; i < 8; i++) {
            int v = tid + (i << 7);
            int r = v >> 3, q = v & 7;
            float4 t = *(const float4*)(Ab + (long)r * lda + (q << 2));
            __nv_bfloat162 h01, h23, l01, l23;
            h01.x = __float2bfloat16(t.x); h01.y = __float2bfloat16(t.y);
            h23.x = __float2bfloat16(t.z); h23.y = __float2bfloat16(t.w);
            l01.x = __float2bfloat16(t.x - __bfloat162float(h01.x));
            l01.y = __float2bfloat16(t.y - __bfloat162float(h01.y));
            l23.x = __float2bfloat16(t.z - __bfloat162float(h23.x));
            l23.y = __float2bfloat16(t.w - __bfloat162float(h23.y));
            int o = r * 40 + (q << 2);
            *(uint2*)(&sAh[o]) = make_uint2(*(uint32_t*)&h01, *(uint32_t*)&h23);
            *(uint2*)(&sAl[o]) = make_uint2(*(uint32_t*)&l01, *(uint32_t*)&l23);
        }
        // ---- stage B [64 x 32] pre-split bf16 ----
#pragma unroll
        for (int i = 0; i < 2; i++) {
            int v = tid + (i << 7);
            int n = v >> 2, q = v & 3;
            uint4 th = make_uint4(0, 0, 0, 0), tl = make_uint4(0, 0, 0, 0);
            if (n0 + n < N) {
                long o = (long)n * K + k0 + (q << 3);
                th = *(const uint4*)(WHg + o);
                tl = *(const uint4*)(WLg + o);
            }
            int so = n * 40 + (q << 3);
            *(uint4*)(&sBh[so]) = th;
            *(uint4*)(&sBl[so]) = tl;
        }
        __syncthreads();

        // ---- compute: 2 k-steps of 16 ----
#pragma unroll
        for (int s = 0; s < 2; s++) {
            uint32_t ah[16], al[16], bh[8], bl[8];
#pragma unroll
            for (int mt = 0; mt < 4; mt++) {
                uint32_t ad = a_off + mt * (16 * 80) + s * 32;
                ldsm4(&ah[mt * 4], aBh + ad);
                ldsm4(&al[mt * 4], aBl + ad);
            }
#pragma unroll
            for (int p = 0; p < 2; p++) {
                uint32_t bd = b_off + p * (16 * 80) + s * 32;
                ldsm4(&bh[p * 4], bBh + bd);
                ldsm4(&bl[p * 4], bBl + bd);
            }
#pragma unroll
            for (int mt = 0; mt < 4; mt++)
#pragma unroll
                for (int nt = 0; nt < 4; nt++) {
                    float* c = &acc[(mt * 4 + nt) * 4];
                    mma_bf16(c, &ah[mt * 4], &bh[nt * 2]);  // hi*hi
                    mma_bf16(c, &ah[mt * 4], &bl[nt * 2]);  // hi*lo
                    mma_bf16(c, &al[mt * 4], &bh[nt * 2]);  // lo*hi
                }
        }
    }

    // ---- epilogue: bias + activation ----
    const int quad = L >> 2, ql = L & 3;
    float* Cg = C + (long)g * cGrp;
#pragma unroll
    for (int mt = 0; mt < 4; mt++) {
        int row = m0 + wr * 64 + mt * 16 + quad;
#pragma unroll
        for (int nt = 0; nt < 4; nt++) {
            int lc = wc * 32 + nt * 8 + (ql << 1);
            int col = n0 + lc;
            if (col < N) {
                const float* c = &acc[(mt * 4 + nt) * 4];
                float b0 = sBias[lc], b1 = sBias[lc + 1];
                float2 v0 = make_float2(c[0] + b0, c[1] + b1);
                float2 v1 = make_float2(c[2] + b0, c[3] + b1);
                if (ACT == 1) {
                    v0.x = fmaxf(v0.x, 0.f); v0.y = fmaxf(v0.y, 0.f);
                    v1.x = fmaxf(v1.x, 0.f); v1.y = fmaxf(v1.y, 0.f);
                }
                if (ACT == 2) {
                    v0.x = tanhf(v0.x); v0.y = tanhf(v0.y);
                    v1.x = tanhf(v1.x); v1.y = tanhf(v1.y);
                }
                *(float2*)(Cg + (long)row * ldc + col) = v0;
                *(float2*)(Cg + (long)(row + 8) * ldc + col) = v1;
            }
        }
    }
}

// ---------------- host side -------------------------------------------------
template <int ACT>
static void launch_gemm(const float* A, long aGrp, int lda,
                        const __nv_bfloat16* whi, const __nv_bfloat16* wlo,
                        long wGrp, const float* bias, long bGrp,
                        float* C, long cGrp, int ldc, int N, int K, int G) {
    dim3 grid((N + 63) / 64, BATCH / 128, G);
    gemm_mma<ACT><<<grid, 128>>>(A, aGrp, lda, whi, wlo, wGrp, bias, bGrp, C,
                                 cGrp, ldc, N, K);
}

extern "C" void kernel_launch(void* const* d_in, const int* in_sizes, int n_in,
                              void* d_out, int out_size) {
    const float* in[31];
    for (int i = 0; i < 31; i++) in[i] = (const float*)d_in[i];
    const float* state = in[0];
    const float *enc_w1 = in[1], *enc_b1 = in[2], *enc_wh = in[3],
                *enc_bh = in[4], *enc_wo = in[5], *enc_bo = in[6];
    const float *a0w1 = in[7], *a0b1 = in[8], *a0wh = in[9], *a0bh = in[10],
                *a0wo = in[11], *a0bo = in[12];
    const float *a1w1 = in[13], *a1b1 = in[14], *a1wh = in[15], *a1bh = in[16],
                *a1wo = in[17], *a1bo = in[18];
    const float *a2w1 = in[19], *a2b1 = in[20], *a2wh = in[21], *a2bh = in[22],
                *a2wo = in[23], *a2bo = in[24];
    const float *hw1 = in[25], *hb1 = in[26], *hwh = in[27], *hbh = in[28],
                *hwo = in[29], *hbo = in[30];

    float* emb = (float*)d_out;                    // [4096, 85, 128]
    float* action = emb + (long)BATCH * 85 * 128;  // [4096, 32]

    float *h1, *h2;
    __nv_bfloat16 *whi, *wlo;
    cudaGetSymbolAddress((void**)&h1, g_h1);
    cudaGetSymbolAddress((void**)&h2, g_h2);
    cudaGetSymbolAddress((void**)&whi, g_whi);
    cudaGetSymbolAddress((void**)&wlo, g_wlo);

    // scratch offsets (elements), [N,K] per group
    const long o_e1 = 0;
    const long o_eh = 2097152;
    const long o_eo = 3145728;
    const long o_01 = 4194304;
    const long o_0h = 8388608;
    const long o_0o = 12582912;
    const long o_11 = 13631488;
    const long o_1h = 14680064;
    const long o_1o = 15728640;
    const long o_21 = 15990784;
    const long o_2h = 16252928;
    const long o_2o = 16515072;
    const long o_h1 = 16580608;
    const long o_hh = 16596992;
    const long o_ho = 16613376;

    dim3 tb(32, 8);
    prep_w<<<dim3(4, 8, 64), tb>>>(enc_w1, whi + o_e1, wlo + o_e1, 256, 128);
    prep_w<<<dim3(4, 4, 64), tb>>>(enc_wh, whi + o_eh, wlo + o_eh, 128, 128);
    prep_w<<<dim3(4, 4, 64), tb>>>(enc_wo, whi + o_eo, wlo + o_eo, 128, 128);
    prep_w<<<dim3(16, 16, 16), tb>>>(a0w1, whi + o_01, wlo + o_01, 512, 512);
    prep_w<<<dim3(16, 16, 16), tb>>>(a0wh, whi + o_0h, wlo + o_0h, 512, 512);
    prep_w<<<dim3(4, 16, 16), tb>>>(a0wo, whi + o_0o, wlo + o_0o, 512, 128);
    prep_w<<<dim3(16, 16, 4), tb>>>(a1w1, whi + o_11, wlo + o_11, 512, 512);
    prep_w<<<dim3(16, 16, 4), tb>>>(a1wh, whi + o_1h, wlo + o_1h, 512, 512);
    prep_w<<<dim3(4, 16, 4), tb>>>(a1wo, whi + o_1o, wlo + o_1o, 512, 128);
    prep_w<<<dim3(16, 16, 1), tb>>>(a2w1, whi + o_21, wlo + o_21, 512, 512);
    prep_w<<<dim3(16, 16, 1), tb>>>(a2wh, whi + o_2h, wlo + o_2h, 512, 512);
    prep_w<<<dim3(4, 16, 1), tb>>>(a2wo, whi + o_2o, wlo + o_2o, 512, 128);
    prep_w<<<dim3(4, 4, 1), tb>>>(hw1, whi + o_h1, wlo + o_h1, 128, 128);
    prep_w<<<dim3(4, 4, 1), tb>>>(hwh, whi + o_hh, wlo + o_hh, 128, 128);
    prep_w<<<dim3(1, 4, 1), tb>>>(hwo, whi + o_ho, wlo + o_ho, 128, 32);

    const int D = 128, CD = 512;
    // encoders (G=64): state[B,256] -> 128 -> 128 -> emb nodes 0..63
    launch_gemm<1>(state, 0L, 256, whi + o_e1, wlo + o_e1, 128L * 256, enc_b1,
                   D, h1, (long)BATCH * D, D, D, 256, 64);
    launch_gemm<1>(h1, (long)BATCH * D, D, whi + o_eh, wlo + o_eh, 128L * 128,
                   enc_bh, D, h2, (long)BATCH * D, D, D, 128, 64);
    launch_gemm<0>(h2, (long)BATCH * D, D, whi + o_eo, wlo + o_eo, 128L * 128,
                   enc_bo, D, emb, (long)D, LDE, D, 128, 64);
    // agg0 (G=16)
    launch_gemm<1>(emb, 512L, LDE, whi + o_01, wlo + o_01, 512L * 512, a0b1, CD,
                   h1, (long)BATCH * CD, CD, CD, 512, 16);
    launch_gemm<1>(h1, (long)BATCH * CD, CD, whi + o_0h, wlo + o_0h, 512L * 512,
                   a0bh, CD, h2, (long)BATCH * CD, CD, CD, 512, 16);
    launch_gemm<0>(h2, (long)BATCH * CD, CD, whi + o_0o, wlo + o_0o, 128L * 512,
                   a0bo, D, emb + 64 * 128, (long)D, LDE, D, 512, 16);
    // agg1 (G=4)
    launch_gemm<1>(emb + 64 * 128, 512L, LDE, whi + o_11, wlo + o_11,
                   512L * 512, a1b1, CD, h1, (long)BATCH * CD, CD, CD, 512, 4);
    launch_gemm<1>(h1, (long)BATCH * CD, CD, whi + o_1h, wlo + o_1h, 512L * 512,
                   a1bh, CD, h2, (long)BATCH * CD, CD, CD, 512, 4);
    launch_gemm<0>(h2, (long)BATCH * CD, CD, whi + o_1o, wlo + o_1o, 128L * 512,
                   a1bo, D, emb + 80 * 128, (long)D, LDE, D, 512, 4);
    // agg2 (G=1)
    launch_gemm<1>(emb + 80 * 128, 0L, LDE, whi + o_21, wlo + o_21, 0L, a2b1,
                   0L, h1, 0L, CD, CD, 512, 1);
    launch_gemm<1>(h1, 0L, CD, whi + o_2h, wlo + o_2h, 0L, a2bh, 0L, h2, 0L,
                   CD, CD, 512, 1);
    launch_gemm<0>(h2, 0L, CD, whi + o_2o, wlo + o_2o, 0L, a2bo, 0L,
                   emb + 84 * 128, 0L, LDE, D, 512, 1);
    // head (G=1)
    launch_gemm<1>(emb + 84 * 128, 0L, LDE, whi + o_h1, wlo + o_h1, 0L, hb1, 0L,
                   h1, 0L, D, D, 128, 1);
    launch_gemm<1>(h1, 0L, D, whi + o_hh, wlo + o_hh, 0L, hbh, 0L, h2, 0L, D, D,
                   128, 1);
    launch_gemm<2>(h2, 0L, D, whi + o_ho, wlo + o_ho, 0L, hbo, 0L, action, 0L,
                   32, 32, 128, 1);
}

// round 8
// speedup vs baseline: 2.5992x; 1.0636x over previous
#include <cuda_runtime.h>
#include <cuda_bf16.h>
#include <cstdint>
#include <math.h>

// ===========================================================================
// Actor_15324443312913 — HMMA bf16 hi/lo-split grouped GEMM, round 8.
//  * all inter-layer activations stored as PRE-SPLIT bf16 hi/lo pairs
//    (split happens once, in the producing GEMM's epilogue)
//  * cp.async double-buffered mainloop, tile 128x128, 256 thr
//  * embeds fp32 [B,85,128] written only by embed-producing layers; a bf16
//    hi/lo mirror "tree" feeds the next level.
// ===========================================================================

#define BATCH 4096
#define LDE   (85 * 128)

#define WT_TOTAL 16617472
__device__ __nv_bfloat16 g_whi[WT_TOTAL];
__device__ __nv_bfloat16 g_wlo[WT_TOTAL];
// hidden activations (bf16 pairs), max 16*4096*512
__device__ __nv_bfloat16 g_h1h[33554432], g_h1l[33554432];
__device__ __nv_bfloat16 g_h2h[33554432], g_h2l[33554432];
// bf16 mirror of the embeds tree [B, 85*128]
__device__ __nv_bfloat16 g_th[44564480], g_tl[44564480];
// split state [B,256]
__device__ __nv_bfloat16 g_sh[1048576], g_sl[1048576];

// ---------------- helpers ---------------------------------------------------
__device__ __forceinline__ uint32_t smem_u32(const void* p) {
    uint32_t a;
    asm("{ .reg .u64 t; cvta.to.shared.u64 t, %1; cvt.u32.u64 %0, t; }"
        : "=r"(a) : "l"(p));
    return a;
}
__device__ __forceinline__ void ldsm4(uint32_t* r, uint32_t addr) {
    asm volatile("ldmatrix.sync.aligned.m8n8.x4.shared.b16 {%0,%1,%2,%3}, [%4];"
                 : "=r"(r[0]), "=r"(r[1]), "=r"(r[2]), "=r"(r[3]) : "r"(addr));
}
__device__ __forceinline__ void mma_bf16(float* c, const uint32_t* a,
                                         const uint32_t* b) {
    asm volatile(
        "mma.sync.aligned.m16n8k16.row.col.f32.bf16.bf16.f32 "
        "{%0,%1,%2,%3},{%4,%5,%6,%7},{%8,%9},{%0,%1,%2,%3};"
        : "+f"(c[0]), "+f"(c[1]), "+f"(c[2]), "+f"(c[3])
        : "r"(a[0]), "r"(a[1]), "r"(a[2]), "r"(a[3]), "r"(b[0]), "r"(b[1]));
}
__device__ __forceinline__ void cpa16(uint32_t dst, const void* src, bool p) {
    int sz = p ? 16 : 0;
    asm volatile("cp.async.cg.shared.global [%0], [%1], 16, %2;"
                 :: "r"(dst), "l"(src), "r"(sz));
}
__device__ __forceinline__ void split2(float x, float y, uint32_t& h2,
                                       uint32_t& l2) {
    __nv_bfloat162 h, l;
    h.x = __float2bfloat16(x); h.y = __float2bfloat16(y);
    l.x = __float2bfloat16(x - __bfloat162float(h.x));
    l.y = __float2bfloat16(y - __bfloat162float(h.y));
    h2 = *(uint32_t*)&h;
    l2 = *(uint32_t*)&l;
}

// ---------------- weight prep: transpose [K,N] -> [N,K] + hi/lo split ------
__global__ void prep_w(const float* __restrict__ in,
                       __nv_bfloat16* __restrict__ hi,
                       __nv_bfloat16* __restrict__ lo, int K, int N) {
    __shared__ float t[32][33];
    const long grp = (long)K * N;
    const float* ing = in + blockIdx.z * grp;
    __nv_bfloat16* hig = hi + blockIdx.z * grp;
    __nv_bfloat16* log_ = lo + blockIdx.z * grp;
    int n0 = blockIdx.x * 32, k0 = blockIdx.y * 32;
    int tx = threadIdx.x, ty = threadIdx.y;
#pragma unroll
    for (int i = 0; i < 32; i += 8)
        t[ty + i][tx] = ing[(long)(k0 + ty + i) * N + n0 + tx];
    __syncthreads();
#pragma unroll
    for (int i = 0; i < 32; i += 8) {
        float v = t[tx][ty + i];
        __nv_bfloat16 h = __float2bfloat16(v);
        float r = v - __bfloat162float(h);
        long o = (long)(n0 + ty + i) * K + k0 + tx;
        hig[o] = h;
        log_[o] = __float2bfloat16(r);
    }
}

// ---------------- split fp32 vector -> bf16 hi/lo ---------------------------
__global__ void cvt_split(const float* __restrict__ in,
                          __nv_bfloat16* __restrict__ hi,
                          __nv_bfloat16* __restrict__ lo, int n4) {
    int i = blockIdx.x * blockDim.x + threadIdx.x;
    if (i < n4) {
        float4 t = ((const float4*)in)[i];
        uint32_t h01, l01, h23, l23;
        split2(t.x, t.y, h01, l01);
        split2(t.z, t.w, h23, l23);
        ((uint2*)hi)[i] = make_uint2(h01, h23);
        ((uint2*)lo)[i] = make_uint2(l01, l23);
    }
}

// ---------------- main GEMM kernel -----------------------------------------
// CTA 256 thr = 8 warps (2 x 4); tile M128 x N128, K-chunk 32, double-buffered
// cp.async. smem rows padded to 40 bf16 (80 B).
// Stage layout (per stage, 40960 B): Ah[128x40] Al[128x40] Bh[128x40] Bl[128x40]
#define STAGE_BYTES 40960
#define SMEM_BYTES  (2 * STAGE_BYTES + 512)

__device__ __forceinline__ void stage_tiles(
    uint32_t sb, const __nv_bfloat16* Ahg, const __nv_bfloat16* Alg, int lda,
    const __nv_bfloat16* WHg, const __nv_bfloat16* WLg, int K, int k0, int n0,
    int N, int tid) {
#pragma unroll
    for (int i = 0; i < 2; i++) {
        int v = tid + (i << 8);
        int r = v >> 2, q = v & 3;
        uint32_t d = (uint32_t)(r * 80 + (q << 4));
        long ao = (long)r * lda + k0 + (q << 3);
        cpa16(sb + d, Ahg + ao, true);
        cpa16(sb + 10240 + d, Alg + ao, true);
        bool bp = (n0 + r) < N;
        long bo = bp ? ((long)r * K + k0 + (q << 3)) : 0;
        cpa16(sb + 20480 + d, WHg + bo, bp);
        cpa16(sb + 30720 + d, WLg + bo, bp);
    }
}

template <int ACT, bool WF32, bool WB16>  // ACT: 0 none 1 relu 2 tanh
__global__ __launch_bounds__(256, 2)
void gemm2(const __nv_bfloat16* __restrict__ Ah,
           const __nv_bfloat16* __restrict__ Al, long aGrp, int lda,
           const __nv_bfloat16* __restrict__ WH,
           const __nv_bfloat16* __restrict__ WL, long wGrp,
           const float* __restrict__ Bias, long bGrp,
           float* __restrict__ Cf, long cfGrp, int ldcf,
           __nv_bfloat16* __restrict__ OH, __nv_bfloat16* __restrict__ OL,
           long oGrp, int ldo, int N, int K) {
    extern __shared__ char smem[];
    const uint32_t sbs = smem_u32(smem);
    float* sBias = (float*)(smem + 2 * STAGE_BYTES);

    const int tid = threadIdx.x, w = tid >> 5, L = tid & 31;
    const int wr = w >> 2, wc = w & 3;
    const int g = blockIdx.z;
    const int m0 = blockIdx.y * 128, n0 = blockIdx.x * 128;

    const __nv_bfloat16* Ahg = Ah + (long)g * aGrp + (long)m0 * lda;
    const __nv_bfloat16* Alg = Al + (long)g * aGrp + (long)m0 * lda;
    const __nv_bfloat16* WHg = WH + (long)g * wGrp + (long)n0 * K;
    const __nv_bfloat16* WLg = WL + (long)g * wGrp + (long)n0 * K;

    if (tid < 128) {
        int c = n0 + tid;
        sBias[tid] = (c < N) ? Bias[(long)g * bGrp + c] : 0.f;
    }

    float acc[64];
#pragma unroll
    for (int i = 0; i < 64; i++) acc[i] = 0.f;

    const uint32_t a_off =
        (uint32_t)((wr * 64 + (L & 7) + ((L >> 3) & 1) * 8) * 80 +
                   ((L >> 4) & 1) * 16);
    const uint32_t b_off =
        (uint32_t)((wc * 32 + (L & 7) + ((L >> 4) & 1) * 8) * 80 +
                   ((L >> 3) & 1) * 16);

    const int nch = K >> 5;
    stage_tiles(sbs, Ahg, Alg, lda, WHg, WLg, K, 0, n0, N, tid);
    asm volatile("cp.async.commit_group;" ::: "memory");

    for (int ch = 0; ch < nch; ch++) {
        if (ch + 1 < nch)
            stage_tiles(sbs + ((ch + 1) & 1) * STAGE_BYTES, Ahg, Alg, lda, WHg,
                        WLg, K, (ch + 1) << 5, n0, N, tid);
        asm volatile("cp.async.commit_group;" ::: "memory");
        asm volatile("cp.async.wait_group 1;" ::: "memory");
        __syncthreads();

        const uint32_t ab = sbs + (ch & 1) * STAGE_BYTES;
        const uint32_t bb = ab + 20480;
#pragma unroll
        for (int s = 0; s < 2; s++) {
            uint32_t ah[16], al[16];
#pragma unroll
            for (int mt = 0; mt < 4; mt++) {
                uint32_t ad = a_off + mt * 1280 + s * 32;
                ldsm4(&ah[mt * 4], ab + ad);
                ldsm4(&al[mt * 4], ab + 10240 + ad);
            }
#pragma unroll
            for (int p = 0; p < 2; p++) {
                uint32_t bh[4], bl[4];
                uint32_t bd = b_off + p * 1280 + s * 32;
                ldsm4(bh, bb + bd);
                ldsm4(bl, bb + 10240 + bd);
#pragma unroll
                for (int mt = 0; mt < 4; mt++)
#pragma unroll
                    for (int t = 0; t < 2; t++) {
                        float* c = &acc[(mt * 4 + p * 2 + t) * 4];
                        mma_bf16(c, &ah[mt * 4], &bh[t * 2]);  // hi*hi
                        mma_bf16(c, &ah[mt * 4], &bl[t * 2]);  // hi*lo
                        mma_bf16(c, &al[mt * 4], &bh[t * 2]);  // lo*hi
                    }
            }
        }
        __syncthreads();
    }

    // ---- epilogue ----
    const int quad = L >> 2, ql = L & 3;
    float* Cfg = Cf + (long)g * cfGrp;
    __nv_bfloat16* OHg = OH + (long)g * oGrp;
    __nv_bfloat16* OLg = OL + (long)g * oGrp;
#pragma unroll
    for (int mt = 0; mt < 4; mt++) {
        int r0 = m0 + wr * 64 + mt * 16 + quad;
#pragma unroll
        for (int nt = 0; nt < 4; nt++) {
            int lc = wc * 32 + nt * 8 + (ql << 1);
            int col = n0 + lc;
            if (col < N) {
                const float* c = &acc[(mt * 4 + nt) * 4];
                float b0 = sBias[lc], b1 = sBias[lc + 1];
                float2 v0 = make_float2(c[0] + b0, c[1] + b1);
                float2 v1 = make_float2(c[2] + b0, c[3] + b1);
                if (ACT == 1) {
                    v0.x = fmaxf(v0.x, 0.f); v0.y = fmaxf(v0.y, 0.f);
                    v1.x = fmaxf(v1.x, 0.f); v1.y = fmaxf(v1.y, 0.f);
                }
                if (ACT == 2) {
                    v0.x = tanhf(v0.x); v0.y = tanhf(v0.y);
                    v1.x = tanhf(v1.x); v1.y = tanhf(v1.y);
                }
                if (WF32) {
                    *(float2*)(Cfg + (long)r0 * ldcf + col) = v0;
                    *(float2*)(Cfg + (long)(r0 + 8) * ldcf + col) = v1;
                }
                if (WB16) {
                    uint32_t h2, l2;
                    split2(v0.x, v0.y, h2, l2);
                    *(uint32_t*)(OHg + (long)r0 * ldo + col) = h2;
                    *(uint32_t*)(OLg + (long)r0 * ldo + col) = l2;
                    split2(v1.x, v1.y, h2, l2);
                    *(uint32_t*)(OHg + (long)(r0 + 8) * ldo + col) = h2;
                    *(uint32_t*)(OLg + (long)(r0 + 8) * ldo + col) = l2;
                }
            }
        }
    }
}

// ---------------- host side -------------------------------------------------
typedef __nv_bfloat16 bf16;

struct GemmArgs {
    const bf16 *Ah, *Al; long aGrp; int lda;
    const bf16 *WH, *WL; long wGrp;
    const float* Bias; long bGrp;
    float* Cf; long cfGrp; int ldcf;
    bf16 *OH, *OL; long oGrp; int ldo;
    int N, K, G;
};

template <int ACT, bool WF32, bool WB16>
static void rungemm(const GemmArgs& a) {
    dim3 grid((a.N + 127) / 128, BATCH / 128, a.G);
    gemm2<ACT, WF32, WB16><<<grid, 256, SMEM_BYTES>>>(
        a.Ah, a.Al, a.aGrp, a.lda, a.WH, a.WL, a.wGrp, a.Bias, a.bGrp, a.Cf,
        a.cfGrp, a.ldcf, a.OH, a.OL, a.oGrp, a.ldo, a.N, a.K);
}

extern "C" void kernel_launch(void* const* d_in, const int* in_sizes, int n_in,
                              void* d_out, int out_size) {
    const float* in[31];
    for (int i = 0; i < 31; i++) in[i] = (const float*)d_in[i];
    const float* state = in[0];

    float* emb = (float*)d_out;                    // [4096, 85, 128]
    float* action = emb + (long)BATCH * 85 * 128;  // [4096, 32]

    bf16 *whi, *wlo, *h1h, *h1l, *h2h, *h2l, *th, *tl, *sh, *sl;
    cudaGetSymbolAddress((void**)&whi, g_whi);
    cudaGetSymbolAddress((void**)&wlo, g_wlo);
    cudaGetSymbolAddress((void**)&h1h, g_h1h);
    cudaGetSymbolAddress((void**)&h1l, g_h1l);
    cudaGetSymbolAddress((void**)&h2h, g_h2h);
    cudaGetSymbolAddress((void**)&h2l, g_h2l);
    cudaGetSymbolAddress((void**)&th, g_th);
    cudaGetSymbolAddress((void**)&tl, g_tl);
    cudaGetSymbolAddress((void**)&sh, g_sh);
    cudaGetSymbolAddress((void**)&sl, g_sl);

    cudaFuncSetAttribute(gemm2<1, false, true>,
                         cudaFuncAttributeMaxDynamicSharedMemorySize, SMEM_BYTES);
    cudaFuncSetAttribute(gemm2<0, true, true>,
                         cudaFuncAttributeMaxDynamicSharedMemorySize, SMEM_BYTES);
    cudaFuncSetAttribute(gemm2<2, true, false>,
                         cudaFuncAttributeMaxDynamicSharedMemorySize, SMEM_BYTES);

    // scratch offsets (elements), [N,K] per group
    const long o_e1 = 0, o_eh = 2097152, o_eo = 3145728;
    const long o_01 = 4194304, o_0h = 8388608, o_0o = 12582912;
    const long o_11 = 13631488, o_1h = 14680064, o_1o = 15728640;
    const long o_21 = 15990784, o_2h = 16252928, o_2o = 16515072;
    const long o_h1 = 16580608, o_hh = 16596992, o_ho = 16613376;

    dim3 tb(32, 8);
    prep_w<<<dim3(4, 8, 64), tb>>>(in[1], whi + o_e1, wlo + o_e1, 256, 128);
    prep_w<<<dim3(4, 4, 64), tb>>>(in[3], whi + o_eh, wlo + o_eh, 128, 128);
    prep_w<<<dim3(4, 4, 64), tb>>>(in[5], whi + o_eo, wlo + o_eo, 128, 128);
    prep_w<<<dim3(16, 16, 16), tb>>>(in[7], whi + o_01, wlo + o_01, 512, 512);
    prep_w<<<dim3(16, 16, 16), tb>>>(in[9], whi + o_0h, wlo + o_0h, 512, 512);
    prep_w<<<dim3(4, 16, 16), tb>>>(in[11], whi + o_0o, wlo + o_0o, 512, 128);
    prep_w<<<dim3(16, 16, 4), tb>>>(in[13], whi + o_11, wlo + o_11, 512, 512);
    prep_w<<<dim3(16, 16, 4), tb>>>(in[15], whi + o_1h, wlo + o_1h, 512, 512);
    prep_w<<<dim3(4, 16, 4), tb>>>(in[17], whi + o_1o, wlo + o_1o, 512, 128);
    prep_w<<<dim3(16, 16, 1), tb>>>(in[19], whi + o_21, wlo + o_21, 512, 512);
    prep_w<<<dim3(16, 16, 1), tb>>>(in[21], whi + o_2h, wlo + o_2h, 512, 512);
    prep_w<<<dim3(4, 16, 1), tb>>>(in[23], whi + o_2o, wlo + o_2o, 512, 128);
    prep_w<<<dim3(4, 4, 1), tb>>>(in[25], whi + o_h1, wlo + o_h1, 128, 128);
    prep_w<<<dim3(4, 4, 1), tb>>>(in[27], whi + o_hh, wlo + o_hh, 128, 128);
    prep_w<<<dim3(1, 4, 1), tb>>>(in[29], whi + o_ho, wlo + o_ho, 128, 32);

    cvt_split<<<1024, 256>>>(state, sh, sl, BATCH * 256 / 4);

    const int D = 128, CD = 512;
    GemmArgs a;

    // encoders (G=64)
    a = {sh, sl, 0L, 256, whi + o_e1, wlo + o_e1, 128L * 256, in[2], D,
         nullptr, 0L, 0, h1h, h1l, (long)BATCH * D, D, D, 256, 64};
    rungemm<1, false, true>(a);
    a = {h1h, h1l, (long)BATCH * D, D, whi + o_eh, wlo + o_eh, 128L * 128,
         in[4], D, nullptr, 0L, 0, h2h, h2l, (long)BATCH * D, D, D, 128, 64};
    rungemm<1, false, true>(a);
    a = {h2h, h2l, (long)BATCH * D, D, whi + o_eo, wlo + o_eo, 128L * 128,
         in[6], D, emb, (long)D, LDE, th, tl, (long)D, LDE, D, 128, 64};
    rungemm<0, true, true>(a);

    // agg0 (G=16)
    a = {th, tl, 512L, LDE, whi + o_01, wlo + o_01, 512L * 512, in[8], CD,
         nullptr, 0L, 0, h1h, h1l, (long)BATCH * CD, CD, CD, 512, 16};
    rungemm<1, false, true>(a);
    a = {h1h, h1l, (long)BATCH * CD, CD, whi + o_0h, wlo + o_0h, 512L * 512,
         in[10], CD, nullptr, 0L, 0, h2h, h2l, (long)BATCH * CD, CD, CD, 512, 16};
    rungemm<1, false, true>(a);
    a = {h2h, h2l, (long)BATCH * CD, CD, whi + o_0o, wlo + o_0o, 128L * 512,
         in[12], D, emb + 64 * 128, (long)D, LDE, th + 64 * 128, tl + 64 * 128,
         (long)D, LDE, D, 512, 16};
    rungemm<0, true, true>(a);

    // agg1 (G=4)
    a = {th + 64 * 128, tl + 64 * 128, 512L, LDE, whi + o_11, wlo + o_11,
         512L * 512, in[14], CD, nullptr, 0L, 0, h1h, h1l, (long)BATCH * CD,
         CD, CD, 512, 4};
    rungemm<1, false, true>(a);
    a = {h1h, h1l, (long)BATCH * CD, CD, whi + o_1h, wlo + o_1h, 512L * 512,
         in[16], CD, nullptr, 0L, 0, h2h, h2l, (long)BATCH * CD, CD, CD, 512, 4};
    rungemm<1, false, true>(a);
    a = {h2h, h2l, (long)BATCH * CD, CD, whi + o_1o, wlo + o_1o, 128L * 512,
         in[18], D, emb + 80 * 128, (long)D, LDE, th + 80 * 128, tl + 80 * 128,
         (long)D, LDE, D, 512, 4};
    rungemm<0, true, true>(a);

    // agg2 (G=1)
    a = {th + 80 * 128, tl + 80 * 128, 0L, LDE, whi + o_21, wlo + o_21, 0L,
         in[20], 0L, nullptr, 0L, 0, h1h, h1l, 0L, CD, CD, 512, 1};
    rungemm<1, false, true>(a);
    a = {h1h, h1l, 0L, CD, whi + o_2h, wlo + o_2h, 0L, in[22], 0L, nullptr, 0L,
         0, h2h, h2l, 0L, CD, CD, 512, 1};
    rungemm<1, false, true>(a);
    a = {h2h, h2l, 0L, CD, whi + o_2o, wlo + o_2o, 0L, in[24], 0L,
         emb + 84 * 128, 0L, LDE, th + 84 * 128, tl + 84 * 128, 0L, LDE, D,
         512, 1};
    rungemm<0, true, true>(a);

    // head (G=1)
    a = {th + 84 * 128, tl + 84 * 128, 0L, LDE, whi + o_h1, wlo + o_h1, 0L,
         in[26], 0L, nullptr, 0L, 0, h1h, h1l, 0L, D, D, 128, 1};
    rungemm<1, false, true>(a);
    a = {h1h, h1l, 0L, D, whi + o_hh, wlo + o_hh, 0L, in[28], 0L, nullptr, 0L,
         0, h2h, h2l, 0L, D, D, 128, 1};
    rungemm<1, false, true>(a);
    a = {h2h, h2l, 0L, D, whi + o_ho, wlo + o_ho, 0L, in[30], 0L, action, 0L,
         32, nullptr, nullptr, 0L, 0, 32, 128, 1};
    rungemm<2, true, false>(a);
}

// round 9
// speedup vs baseline: 2.6331x; 1.0131x over previous
#include <cuda_runtime.h>
#include <cuda_bf16.h>
#include <cstdint>
#include <math.h>

// ===========================================================================
// Actor_15324443312913 — HMMA bf16 hi/lo-split grouped GEMM, round 9.
//  * R8 + : MMA inner loop reordered so consecutive MMAs hit DISTINCT
//    accumulators (break 3-deep RAW chain on acc regs)
//  * all 15 weight-prep launches fused into one table-driven kernel
//    (also aligns ncu -s 5 -c 1 onto the big agg0 GEMM)
// ===========================================================================

#define BATCH 4096
#define LDE   (85 * 128)

typedef __nv_bfloat16 bf16;

#define WT_TOTAL 16617472
__device__ bf16 g_whi[WT_TOTAL];
__device__ bf16 g_wlo[WT_TOTAL];
__device__ bf16 g_h1h[33554432], g_h1l[33554432];
__device__ bf16 g_h2h[33554432], g_h2l[33554432];
__device__ bf16 g_th[44564480], g_tl[44564480];
__device__ bf16 g_sh[1048576], g_sl[1048576];

// ---------------- helpers ---------------------------------------------------
__device__ __forceinline__ uint32_t smem_u32(const void* p) {
    uint32_t a;
    asm("{ .reg .u64 t; cvta.to.shared.u64 t, %1; cvt.u32.u64 %0, t; }"
        : "=r"(a) : "l"(p));
    return a;
}
__device__ __forceinline__ void ldsm4(uint32_t* r, uint32_t addr) {
    asm volatile("ldmatrix.sync.aligned.m8n8.x4.shared.b16 {%0,%1,%2,%3}, [%4];"
                 : "=r"(r[0]), "=r"(r[1]), "=r"(r[2]), "=r"(r[3]) : "r"(addr));
}
__device__ __forceinline__ void mma_bf16(float* c, const uint32_t* a,
                                         const uint32_t* b) {
    asm volatile(
        "mma.sync.aligned.m16n8k16.row.col.f32.bf16.bf16.f32 "
        "{%0,%1,%2,%3},{%4,%5,%6,%7},{%8,%9},{%0,%1,%2,%3};"
        : "+f"(c[0]), "+f"(c[1]), "+f"(c[2]), "+f"(c[3])
        : "r"(a[0]), "r"(a[1]), "r"(a[2]), "r"(a[3]), "r"(b[0]), "r"(b[1]));
}
__device__ __forceinline__ void cpa16(uint32_t dst, const void* src, bool p) {
    int sz = p ? 16 : 0;
    asm volatile("cp.async.cg.shared.global [%0], [%1], 16, %2;"
                 :: "r"(dst), "l"(src), "r"(sz));
}
__device__ __forceinline__ void split2(float x, float y, uint32_t& h2,
                                       uint32_t& l2) {
    __nv_bfloat162 h, l;
    h.x = __float2bfloat16(x); h.y = __float2bfloat16(y);
    l.x = __float2bfloat16(x - __bfloat162float(h.x));
    l.y = __float2bfloat16(y - __bfloat162float(h.y));
    h2 = *(uint32_t*)&h;
    l2 = *(uint32_t*)&l;
}

// ---------------- fused weight prep ----------------------------------------
// One launch: 15 jobs, each transpose [K,N]->[N,K] + hi/lo split.
struct PrepJobs {
    const float* src[15];
    int dstOff[15];
    int K[15], N[15];
    int tileBase[16];  // prefix sums of G*(K/32)*(N/32)
};

__global__ void prep_all(PrepJobs J, bf16* __restrict__ hi,
                         bf16* __restrict__ lo) {
    __shared__ float t[32][33];
    const int bz = blockIdx.x;
    int j = 0;
#pragma unroll
    for (int i = 1; i < 15; i++)
        if (bz >= J.tileBase[i]) j = i;
    const int rem = bz - J.tileBase[j];
    const int K = J.K[j], N = J.N[j];
    const int ntx = N >> 5;
    const int perG = ntx * (K >> 5);
    const int g = rem / perG;
    const int tt = rem % perG;
    const int k0 = (tt / ntx) << 5, n0 = (tt % ntx) << 5;

    const long grp = (long)K * N;
    const float* ing = J.src[j] + (long)g * grp;
    bf16* hig = hi + J.dstOff[j] + (long)g * grp;
    bf16* log_ = lo + J.dstOff[j] + (long)g * grp;
    const int tx = threadIdx.x, ty = threadIdx.y;
#pragma unroll
    for (int i = 0; i < 32; i += 8)
        t[ty + i][tx] = ing[(long)(k0 + ty + i) * N + n0 + tx];
    __syncthreads();
#pragma unroll
    for (int i = 0; i < 32; i += 8) {
        float v = t[tx][ty + i];
        bf16 h = __float2bfloat16(v);
        float r = v - __bfloat162float(h);
        long o = (long)(n0 + ty + i) * K + k0 + tx;
        hig[o] = h;
        log_[o] = __float2bfloat16(r);
    }
}

// ---------------- split fp32 vector -> bf16 hi/lo ---------------------------
__global__ void cvt_split(const float* __restrict__ in,
                          bf16* __restrict__ hi, bf16* __restrict__ lo,
                          int n4) {
    int i = blockIdx.x * blockDim.x + threadIdx.x;
    if (i < n4) {
        float4 t = ((const float4*)in)[i];
        uint32_t h01, l01, h23, l23;
        split2(t.x, t.y, h01, l01);
        split2(t.z, t.w, h23, l23);
        ((uint2*)hi)[i] = make_uint2(h01, h23);
        ((uint2*)lo)[i] = make_uint2(l01, l23);
    }
}

// ---------------- main GEMM kernel -----------------------------------------
#define STAGE_BYTES 40960
#define SMEM_BYTES  (2 * STAGE_BYTES + 512)

__device__ __forceinline__ void stage_tiles(
    uint32_t sb, const bf16* Ahg, const bf16* Alg, int lda, const bf16* WHg,
    const bf16* WLg, int K, int k0, int n0, int N, int tid) {
#pragma unroll
    for (int i = 0; i < 2; i++) {
        int v = tid + (i << 8);
        int r = v >> 2, q = v & 3;
        uint32_t d = (uint32_t)(r * 80 + (q << 4));
        long ao = (long)r * lda + k0 + (q << 3);
        cpa16(sb + d, Ahg + ao, true);
        cpa16(sb + 10240 + d, Alg + ao, true);
        bool bp = (n0 + r) < N;
        long bo = bp ? ((long)r * K + k0 + (q << 3)) : 0;
        cpa16(sb + 20480 + d, WHg + bo, bp);
        cpa16(sb + 30720 + d, WLg + bo, bp);
    }
}

template <int ACT, bool WF32, bool WB16>  // ACT: 0 none 1 relu 2 tanh
__global__ __launch_bounds__(256, 2)
void gemm2(const bf16* __restrict__ Ah, const bf16* __restrict__ Al, long aGrp,
           int lda, const bf16* __restrict__ WH, const bf16* __restrict__ WL,
           long wGrp, const float* __restrict__ Bias, long bGrp,
           float* __restrict__ Cf, long cfGrp, int ldcf,
           bf16* __restrict__ OH, bf16* __restrict__ OL, long oGrp, int ldo,
           int N, int K) {
    extern __shared__ char smem[];
    const uint32_t sbs = smem_u32(smem);
    float* sBias = (float*)(smem + 2 * STAGE_BYTES);

    const int tid = threadIdx.x, w = tid >> 5, L = tid & 31;
    const int wr = w >> 2, wc = w & 3;
    const int g = blockIdx.z;
    const int m0 = blockIdx.y * 128, n0 = blockIdx.x * 128;

    const bf16* Ahg = Ah + (long)g * aGrp + (long)m0 * lda;
    const bf16* Alg = Al + (long)g * aGrp + (long)m0 * lda;
    const bf16* WHg = WH + (long)g * wGrp + (long)n0 * K;
    const bf16* WLg = WL + (long)g * wGrp + (long)n0 * K;

    if (tid < 128) {
        int c = n0 + tid;
        sBias[tid] = (c < N) ? Bias[(long)g * bGrp + c] : 0.f;
    }

    float acc[64];
#pragma unroll
    for (int i = 0; i < 64; i++) acc[i] = 0.f;

    const uint32_t a_off =
        (uint32_t)((wr * 64 + (L & 7) + ((L >> 3) & 1) * 8) * 80 +
                   ((L >> 4) & 1) * 16);
    const uint32_t b_off =
        (uint32_t)((wc * 32 + (L & 7) + ((L >> 4) & 1) * 8) * 80 +
                   ((L >> 3) & 1) * 16);

    const int nch = K >> 5;
    stage_tiles(sbs, Ahg, Alg, lda, WHg, WLg, K, 0, n0, N, tid);
    asm volatile("cp.async.commit_group;" ::: "memory");

    for (int ch = 0; ch < nch; ch++) {
        if (ch + 1 < nch)
            stage_tiles(sbs + ((ch + 1) & 1) * STAGE_BYTES, Ahg, Alg, lda, WHg,
                        WLg, K, (ch + 1) << 5, n0, N, tid);
        asm volatile("cp.async.commit_group;" ::: "memory");
        asm volatile("cp.async.wait_group 1;" ::: "memory");
        __syncthreads();

        const uint32_t ab = sbs + (ch & 1) * STAGE_BYTES;
        const uint32_t bb = ab + 20480;
#pragma unroll
        for (int s = 0; s < 2; s++) {
            uint32_t ah[16], al[16];
#pragma unroll
            for (int mt = 0; mt < 4; mt++) {
                uint32_t ad = a_off + mt * 1280 + s * 32;
                ldsm4(&ah[mt * 4], ab + ad);
                ldsm4(&al[mt * 4], ab + 10240 + ad);
            }
#pragma unroll
            for (int p = 0; p < 2; p++) {
                uint32_t bh[4], bl[4];
                uint32_t bd = b_off + p * 1280 + s * 32;
                ldsm4(bh, bb + bd);
                ldsm4(bl, bb + 10240 + bd);
                // 8 independent accumulators per term group -> no RAW chains
#pragma unroll
                for (int mt = 0; mt < 4; mt++)
#pragma unroll
                    for (int t = 0; t < 2; t++)
                        mma_bf16(&acc[(mt * 4 + p * 2 + t) * 4], &ah[mt * 4],
                                 &bh[t * 2]);  // hi*hi
#pragma unroll
                for (int mt = 0; mt < 4; mt++)
#pragma unroll
                    for (int t = 0; t < 2; t++)
                        mma_bf16(&acc[(mt * 4 + p * 2 + t) * 4], &ah[mt * 4],
                                 &bl[t * 2]);  // hi*lo
#pragma unroll
                for (int mt = 0; mt < 4; mt++)
#pragma unroll
                    for (int t = 0; t < 2; t++)
                        mma_bf16(&acc[(mt * 4 + p * 2 + t) * 4], &al[mt * 4],
                                 &bh[t * 2]);  // lo*hi
            }
        }
        __syncthreads();
    }

    // ---- epilogue ----
    const int quad = L >> 2, ql = L & 3;
    float* Cfg = Cf + (long)g * cfGrp;
    bf16* OHg = OH + (long)g * oGrp;
    bf16* OLg = OL + (long)g * oGrp;
#pragma unroll
    for (int mt = 0; mt < 4; mt++) {
        int r0 = m0 + wr * 64 + mt * 16 + quad;
#pragma unroll
        for (int nt = 0; nt < 4; nt++) {
            int lc = wc * 32 + nt * 8 + (ql << 1);
            int col = n0 + lc;
            if (col < N) {
                const float* c = &acc[(mt * 4 + nt) * 4];
                float b0 = sBias[lc], b1 = sBias[lc + 1];
                float2 v0 = make_float2(c[0] + b0, c[1] + b1);
                float2 v1 = make_float2(c[2] + b0, c[3] + b1);
                if (ACT == 1) {
                    v0.x = fmaxf(v0.x, 0.f); v0.y = fmaxf(v0.y, 0.f);
                    v1.x = fmaxf(v1.x, 0.f); v1.y = fmaxf(v1.y, 0.f);
                }
                if (ACT == 2) {
                    v0.x = tanhf(v0.x); v0.y = tanhf(v0.y);
                    v1.x = tanhf(v1.x); v1.y = tanhf(v1.y);
                }
                if (WF32) {
                    *(float2*)(Cfg + (long)r0 * ldcf + col) = v0;
                    *(float2*)(Cfg + (long)(r0 + 8) * ldcf + col) = v1;
                }
                if (WB16) {
                    uint32_t h2, l2;
                    split2(v0.x, v0.y, h2, l2);
                    *(uint32_t*)(OHg + (long)r0 * ldo + col) = h2;
                    *(uint32_t*)(OLg + (long)r0 * ldo + col) = l2;
                    split2(v1.x, v1.y, h2, l2);
                    *(uint32_t*)(OHg + (long)(r0 + 8) * ldo + col) = h2;
                    *(uint32_t*)(OLg + (long)(r0 + 8) * ldo + col) = l2;
                }
            }
        }
    }
}

// ---------------- host side -------------------------------------------------
struct GemmArgs {
    const bf16 *Ah, *Al; long aGrp; int lda;
    const bf16 *WH, *WL; long wGrp;
    const float* Bias; long bGrp;
    float* Cf; long cfGrp; int ldcf;
    bf16 *OH, *OL; long oGrp; int ldo;
    int N, K, G;
};

template <int ACT, bool WF32, bool WB16>
static void rungemm(const GemmArgs& a) {
    dim3 grid((a.N + 127) / 128, BATCH / 128, a.G);
    gemm2<ACT, WF32, WB16><<<grid, 256, SMEM_BYTES>>>(
        a.Ah, a.Al, a.aGrp, a.lda, a.WH, a.WL, a.wGrp, a.Bias, a.bGrp, a.Cf,
        a.cfGrp, a.ldcf, a.OH, a.OL, a.oGrp, a.ldo, a.N, a.K);
}

extern "C" void kernel_launch(void* const* d_in, const int* in_sizes, int n_in,
                              void* d_out, int out_size) {
    const float* in[31];
    for (int i = 0; i < 31; i++) in[i] = (const float*)d_in[i];
    const float* state = in[0];

    float* emb = (float*)d_out;                    // [4096, 85, 128]
    float* action = emb + (long)BATCH * 85 * 128;  // [4096, 32]

    bf16 *whi, *wlo, *h1h, *h1l, *h2h, *h2l, *th, *tl, *sh, *sl;
    cudaGetSymbolAddress((void**)&whi, g_whi);
    cudaGetSymbolAddress((void**)&wlo, g_wlo);
    cudaGetSymbolAddress((void**)&h1h, g_h1h);
    cudaGetSymbolAddress((void**)&h1l, g_h1l);
    cudaGetSymbolAddress((void**)&h2h, g_h2h);
    cudaGetSymbolAddress((void**)&h2l, g_h2l);
    cudaGetSymbolAddress((void**)&th, g_th);
    cudaGetSymbolAddress((void**)&tl, g_tl);
    cudaGetSymbolAddress((void**)&sh, g_sh);
    cudaGetSymbolAddress((void**)&sl, g_sl);

    cudaFuncSetAttribute(gemm2<1, false, true>,
                         cudaFuncAttributeMaxDynamicSharedMemorySize, SMEM_BYTES);
    cudaFuncSetAttribute(gemm2<0, true, true>,
                         cudaFuncAttributeMaxDynamicSharedMemorySize, SMEM_BYTES);
    cudaFuncSetAttribute(gemm2<2, true, false>,
                         cudaFuncAttributeMaxDynamicSharedMemorySize, SMEM_BYTES);

    // scratch offsets (elements), [N,K] per group
    const int o_e1 = 0, o_eh = 2097152, o_eo = 3145728;
    const int o_01 = 4194304, o_0h = 8388608, o_0o = 12582912;
    const int o_11 = 13631488, o_1h = 14680064, o_1o = 15728640;
    const int o_21 = 15990784, o_2h = 16252928, o_2o = 16515072;
    const int o_h1 = 16580608, o_hh = 16596992, o_ho = 16613376;

    // ---- fused prep: 15 jobs, one launch ----
    PrepJobs J;
    const int srcIdx[15] = {1, 3, 5, 7, 9, 11, 13, 15, 17, 19, 21, 23, 25, 27, 29};
    const int dofs[15] = {o_e1, o_eh, o_eo, o_01, o_0h, o_0o, o_11, o_1h,
                          o_1o, o_21, o_2h, o_2o, o_h1, o_hh, o_ho};
    const int Ks[15] = {256, 128, 128, 512, 512, 512, 512, 512,
                        512, 512, 512, 512, 128, 128, 128};
    const int Ns[15] = {128, 128, 128, 512, 512, 128, 512, 512,
                        128, 512, 512, 128, 128, 128, 32};
    const int Gs[15] = {64, 64, 64, 16, 16, 16, 4, 4, 4, 1, 1, 1, 1, 1, 1};
    int base = 0;
    for (int i = 0; i < 15; i++) {
        J.src[i] = in[srcIdx[i]];
        J.dstOff[i] = dofs[i];
        J.K[i] = Ks[i];
        J.N[i] = Ns[i];
        J.tileBase[i] = base;
        base += Gs[i] * (Ks[i] >> 5) * (Ns[i] >> 5);
    }
    J.tileBase[15] = base;
    prep_all<<<base, dim3(32, 8)>>>(J, whi, wlo);          // launch 1
    cvt_split<<<1024, 256>>>(state, sh, sl, BATCH * 256 / 4);  // launch 2

    const int D = 128, CD = 512;
    GemmArgs a;

    // encoders (G=64)                                      launches 3,4,5
    a = {sh, sl, 0L, 256, whi + o_e1, wlo + o_e1, 128L * 256, in[2], D,
         nullptr, 0L, 0, h1h, h1l, (long)BATCH * D, D, D, 256, 64};
    rungemm<1, false, true>(a);
    a = {h1h, h1l, (long)BATCH * D, D, whi + o_eh, wlo + o_eh, 128L * 128,
         in[4], D, nullptr, 0L, 0, h2h, h2l, (long)BATCH * D, D, D, 128, 64};
    rungemm<1, false, true>(a);
    a = {h2h, h2l, (long)BATCH * D, D, whi + o_eo, wlo + o_eo, 128L * 128,
         in[6], D, emb, (long)D, LDE, th, tl, (long)D, LDE, D, 128, 64};
    rungemm<0, true, true>(a);

    // agg0 (G=16)                                          launch 6 = ncu target
    a = {th, tl, 512L, LDE, whi + o_01, wlo + o_01, 512L * 512, in[8], CD,
         nullptr, 0L, 0, h1h, h1l, (long)BATCH * CD, CD, CD, 512, 16};
    rungemm<1, false, true>(a);
    a = {h1h, h1l, (long)BATCH * CD, CD, whi + o_0h, wlo + o_0h, 512L * 512,
         in[10], CD, nullptr, 0L, 0, h2h, h2l, (long)BATCH * CD, CD, CD, 512, 16};
    rungemm<1, false, true>(a);
    a = {h2h, h2l, (long)BATCH * CD, CD, whi + o_0o, wlo + o_0o, 128L * 512,
         in[12], D, emb + 64 * 128, (long)D, LDE, th + 64 * 128, tl + 64 * 128,
         (long)D, LDE, D, 512, 16};
    rungemm<0, true, true>(a);

    // agg1 (G=4)
    a = {th + 64 * 128, tl + 64 * 128, 512L, LDE, whi + o_11, wlo + o_11,
         512L * 512, in[14], CD, nullptr, 0L, 0, h1h, h1l, (long)BATCH * CD,
         CD, CD, 512, 4};
    rungemm<1, false, true>(a);
    a = {h1h, h1l, (long)BATCH * CD, CD, whi + o_1h, wlo + o_1h, 512L * 512,
         in[16], CD, nullptr, 0L, 0, h2h, h2l, (long)BATCH * CD, CD, CD, 512, 4};
    rungemm<1, false, true>(a);
    a = {h2h, h2l, (long)BATCH * CD, CD, whi + o_1o, wlo + o_1o, 128L * 512,
         in[18], D, emb + 80 * 128, (long)D, LDE, th + 80 * 128, tl + 80 * 128,
         (long)D, LDE, D, 512, 4};
    rungemm<0, true, true>(a);

    // agg2 (G=1)
    a = {th + 80 * 128, tl + 80 * 128, 0L, LDE, whi + o_21, wlo + o_21, 0L,
         in[20], 0L, nullptr, 0L, 0, h1h, h1l, 0L, CD, CD, 512, 1};
    rungemm<1, false, true>(a);
    a = {h1h, h1l, 0L, CD, whi + o_2h, wlo + o_2h, 0L, in[22], 0L, nullptr, 0L,
         0, h2h, h2l, 0L, CD, CD, 512, 1};
    rungemm<1, false, true>(a);
    a = {h2h, h2l, 0L, CD, whi + o_2o, wlo + o_2o, 0L, in[24], 0L,
         emb + 84 * 128, 0L, LDE, th + 84 * 128, tl + 84 * 128, 0L, LDE, D,
         512, 1};
    rungemm<0, true, true>(a);

    // head (G=1)
    a = {th + 84 * 128, tl + 84 * 128, 0L, LDE, whi + o_h1, wlo + o_h1, 0L,
         in[26], 0L, nullptr, 0L, 0, h1h, h1l, 0L, D, D, 128, 1};
    rungemm<1, false, true>(a);
    a = {h1h, h1l, 0L, D, whi + o_hh, wlo + o_hh, 0L, in[28], 0L, nullptr, 0L,
         0, h2h, h2l, 0L, D, D, 128, 1};
    rungemm<1, false, true>(a);
    a = {h2h, h2l, 0L, D, whi + o_ho, wlo + o_ho, 0L, in[30], 0L, action, 0L,
         32, nullptr, nullptr, 0L, 0, 32, 128, 1};
    rungemm<2, true, false>(a);
}

// round 11
// speedup vs baseline: 2.6836x; 1.0192x over previous
#include <cuda_runtime.h>
#include <cuda_bf16.h>
#include <cstdint>
#include <math.h>

// ===========================================================================
// Actor_15324443312913 — HMMA bf16 hi/lo-split grouped GEMM, round 11
// (identical to round 10; that round died to a broker infra failure before
//  ever compiling, so this re-benches the same candidate).
//  * single __syncthreads per K-chunk (wait -> sync -> stage -> compute)
//  * all ldsm hoisted ahead of the MMA burst (B first, then A)
//  * SMALL 64x64 kernel for tail layers (agg1o, agg2*, head*) -> 4x grid
// ===========================================================================

#define BATCH 4096
#define LDE   (85 * 128)

typedef __nv_bfloat16 bf16;

#define WT_TOTAL 16617472
__device__ bf16 g_whi[WT_TOTAL];
__device__ bf16 g_wlo[WT_TOTAL];
__device__ bf16 g_h1h[33554432], g_h1l[33554432];
__device__ bf16 g_h2h[33554432], g_h2l[33554432];
__device__ bf16 g_th[44564480], g_tl[44564480];
__device__ bf16 g_sh[1048576], g_sl[1048576];

// ---------------- helpers ---------------------------------------------------
__device__ __forceinline__ uint32_t smem_u32(const void* p) {
    uint32_t a;
    asm("{ .reg .u64 t; cvta.to.shared.u64 t, %1; cvt.u32.u64 %0, t; }"
        : "=r"(a) : "l"(p));
    return a;
}
__device__ __forceinline__ void ldsm4(uint32_t* r, uint32_t addr) {
    asm volatile("ldmatrix.sync.aligned.m8n8.x4.shared.b16 {%0,%1,%2,%3}, [%4];"
                 : "=r"(r[0]), "=r"(r[1]), "=r"(r[2]), "=r"(r[3]) : "r"(addr));
}
__device__ __forceinline__ void mma_bf16(float* c, const uint32_t* a,
                                         const uint32_t* b) {
    asm volatile(
        "mma.sync.aligned.m16n8k16.row.col.f32.bf16.bf16.f32 "
        "{%0,%1,%2,%3},{%4,%5,%6,%7},{%8,%9},{%0,%1,%2,%3};"
        : "+f"(c[0]), "+f"(c[1]), "+f"(c[2]), "+f"(c[3])
        : "r"(a[0]), "r"(a[1]), "r"(a[2]), "r"(a[3]), "r"(b[0]), "r"(b[1]));
}
__device__ __forceinline__ void cpa16(uint32_t dst, const void* src, bool p) {
    int sz = p ? 16 : 0;
    asm volatile("cp.async.cg.shared.global [%0], [%1], 16, %2;"
                 :: "r"(dst), "l"(src), "r"(sz));
}
#define CP_COMMIT() asm volatile("cp.async.commit_group;" ::: "memory")
#define CP_WAIT0()  asm volatile("cp.async.wait_group 0;" ::: "memory")

__device__ __forceinline__ void split2(float x, float y, uint32_t& h2,
                                       uint32_t& l2) {
    __nv_bfloat162 h, l;
    h.x = __float2bfloat16(x); h.y = __float2bfloat16(y);
    l.x = __float2bfloat16(x - __bfloat162float(h.x));
    l.y = __float2bfloat16(y - __bfloat162float(h.y));
    h2 = *(uint32_t*)&h;
    l2 = *(uint32_t*)&l;
}

// ---------------- fused weight prep ----------------------------------------
struct PrepJobs {
    const float* src[15];
    int dstOff[15];
    int K[15], N[15];
    int tileBase[16];
};

__global__ void prep_all(PrepJobs J, bf16* __restrict__ hi,
                         bf16* __restrict__ lo) {
    __shared__ float t[32][33];
    const int bz = blockIdx.x;
    int j = 0;
#pragma unroll
    for (int i = 1; i < 15; i++)
        if (bz >= J.tileBase[i]) j = i;
    const int rem = bz - J.tileBase[j];
    const int K = J.K[j], N = J.N[j];
    const int ntx = N >> 5;
    const int perG = ntx * (K >> 5);
    const int g = rem / perG;
    const int tt = rem % perG;
    const int k0 = (tt / ntx) << 5, n0 = (tt % ntx) << 5;

    const long grp = (long)K * N;
    const float* ing = J.src[j] + (long)g * grp;
    bf16* hig = hi + J.dstOff[j] + (long)g * grp;
    bf16* log_ = lo + J.dstOff[j] + (long)g * grp;
    const int tx = threadIdx.x, ty = threadIdx.y;
#pragma unroll
    for (int i = 0; i < 32; i += 8)
        t[ty + i][tx] = ing[(long)(k0 + ty + i) * N + n0 + tx];
    __syncthreads();
#pragma unroll
    for (int i = 0; i < 32; i += 8) {
        float v = t[tx][ty + i];
        bf16 h = __float2bfloat16(v);
        float r = v - __bfloat162float(h);
        long o = (long)(n0 + ty + i) * K + k0 + tx;
        hig[o] = h;
        log_[o] = __float2bfloat16(r);
    }
}

__global__ void cvt_split(const float* __restrict__ in, bf16* __restrict__ hi,
                          bf16* __restrict__ lo, int n4) {
    int i = blockIdx.x * blockDim.x + threadIdx.x;
    if (i < n4) {
        float4 t = ((const float4*)in)[i];
        uint32_t h01, l01, h23, l23;
        split2(t.x, t.y, h01, l01);
        split2(t.z, t.w, h23, l23);
        ((uint2*)hi)[i] = make_uint2(h01, h23);
        ((uint2*)lo)[i] = make_uint2(l01, l23);
    }
}

// ---------------- epilogue helper -------------------------------------------
template <int ACT, bool WF32, bool WB16>
__device__ __forceinline__ void epi_store(const float* c, const float* sBias,
                                          int lc, int r0, float* Cfg, int ldcf,
                                          bf16* OHg, bf16* OLg, int ldo,
                                          int col) {
    float b0 = sBias[lc], b1 = sBias[lc + 1];
    float2 v0 = make_float2(c[0] + b0, c[1] + b1);
    float2 v1 = make_float2(c[2] + b0, c[3] + b1);
    if (ACT == 1) {
        v0.x = fmaxf(v0.x, 0.f); v0.y = fmaxf(v0.y, 0.f);
        v1.x = fmaxf(v1.x, 0.f); v1.y = fmaxf(v1.y, 0.f);
    }
    if (ACT == 2) {
        v0.x = tanhf(v0.x); v0.y = tanhf(v0.y);
        v1.x = tanhf(v1.x); v1.y = tanhf(v1.y);
    }
    if (WF32) {
        *(float2*)(Cfg + (long)r0 * ldcf + col) = v0;
        *(float2*)(Cfg + (long)(r0 + 8) * ldcf + col) = v1;
    }
    if (WB16) {
        uint32_t h2, l2;
        split2(v0.x, v0.y, h2, l2);
        *(uint32_t*)(OHg + (long)r0 * ldo + col) = h2;
        *(uint32_t*)(OLg + (long)r0 * ldo + col) = l2;
        split2(v1.x, v1.y, h2, l2);
        *(uint32_t*)(OHg + (long)(r0 + 8) * ldo + col) = h2;
        *(uint32_t*)(OLg + (long)(r0 + 8) * ldo + col) = l2;
    }
}

// ---------------- BIG GEMM: 128x128 tile, 256 thr ---------------------------
#define STAGE_BYTES 40960
#define SMEM_BYTES  (2 * STAGE_BYTES + 512)

__device__ __forceinline__ void stage_tiles(
    uint32_t sb, const bf16* Ahg, const bf16* Alg, int lda, const bf16* WHg,
    const bf16* WLg, int K, int k0, int n0, int N, int tid) {
#pragma unroll
    for (int i = 0; i < 2; i++) {
        int v = tid + (i << 8);
        int r = v >> 2, q = v & 3;
        uint32_t d = (uint32_t)(r * 80 + (q << 4));
        long ao = (long)r * lda + k0 + (q << 3);
        cpa16(sb + d, Ahg + ao, true);
        cpa16(sb + 10240 + d, Alg + ao, true);
        bool bp = (n0 + r) < N;
        long bo = bp ? ((long)r * K + k0 + (q << 3)) : 0;
        cpa16(sb + 20480 + d, WHg + bo, bp);
        cpa16(sb + 30720 + d, WLg + bo, bp);
    }
}

template <int ACT, bool WF32, bool WB16>
__global__ __launch_bounds__(256, 2)
void gemm2(const bf16* __restrict__ Ah, const bf16* __restrict__ Al, long aGrp,
           int lda, const bf16* __restrict__ WH, const bf16* __restrict__ WL,
           long wGrp, const float* __restrict__ Bias, long bGrp,
           float* __restrict__ Cf, long cfGrp, int ldcf,
           bf16* __restrict__ OH, bf16* __restrict__ OL, long oGrp, int ldo,
           int N, int K) {
    extern __shared__ char smem[];
    const uint32_t sbs = smem_u32(smem);
    float* sBias = (float*)(smem + 2 * STAGE_BYTES);

    const int tid = threadIdx.x, w = tid >> 5, L = tid & 31;
    const int wr = w >> 2, wc = w & 3;
    const int g = blockIdx.z;
    const int m0 = blockIdx.y * 128, n0 = blockIdx.x * 128;

    const bf16* Ahg = Ah + (long)g * aGrp + (long)m0 * lda;
    const bf16* Alg = Al + (long)g * aGrp + (long)m0 * lda;
    const bf16* WHg = WH + (long)g * wGrp + (long)n0 * K;
    const bf16* WLg = WL + (long)g * wGrp + (long)n0 * K;

    if (tid < 128) {
        int c = n0 + tid;
        sBias[tid] = (c < N) ? Bias[(long)g * bGrp + c] : 0.f;
    }

    float acc[64];
#pragma unroll
    for (int i = 0; i < 64; i++) acc[i] = 0.f;

    const uint32_t a_off =
        (uint32_t)((wr * 64 + (L & 7) + ((L >> 3) & 1) * 8) * 80 +
                   ((L >> 4) & 1) * 16);
    const uint32_t b_off =
        (uint32_t)((wc * 32 + (L & 7) + ((L >> 4) & 1) * 8) * 80 +
                   ((L >> 3) & 1) * 16);

    const int nch = K >> 5;
    stage_tiles(sbs, Ahg, Alg, lda, WHg, WLg, K, 0, n0, N, tid);
    CP_COMMIT();

    for (int ch = 0; ch < nch; ch++) {
        CP_WAIT0();
        __syncthreads();
        if (ch + 1 < nch)
            stage_tiles(sbs + ((ch + 1) & 1) * STAGE_BYTES, Ahg, Alg, lda, WHg,
                        WLg, K, (ch + 1) << 5, n0, N, tid);
        CP_COMMIT();

        const uint32_t ab = sbs + (ch & 1) * STAGE_BYTES;
        const uint32_t bb = ab + 20480;
#pragma unroll
        for (int s = 0; s < 2; s++) {
            uint32_t ah[16], al[16], bh[8], bl[8];
            // hoist ALL ldsm ahead of the MMA burst (B first, then A)
#pragma unroll
            for (int p = 0; p < 2; p++) {
                uint32_t bd = b_off + p * 1280 + s * 32;
                ldsm4(&bh[p * 4], bb + bd);
                ldsm4(&bl[p * 4], bb + 10240 + bd);
            }
#pragma unroll
            for (int mt = 0; mt < 4; mt++) {
                uint32_t ad = a_off + mt * 1280 + s * 32;
                ldsm4(&ah[mt * 4], ab + ad);
                ldsm4(&al[mt * 4], ab + 10240 + ad);
            }
#pragma unroll
            for (int p = 0; p < 2; p++) {
#pragma unroll
                for (int mt = 0; mt < 4; mt++)
#pragma unroll
                    for (int t = 0; t < 2; t++)
                        mma_bf16(&acc[(mt * 4 + p * 2 + t) * 4], &ah[mt * 4],
                                 &bh[p * 4 + t * 2]);  // hi*hi
#pragma unroll
                for (int mt = 0; mt < 4; mt++)
#pragma unroll
                    for (int t = 0; t < 2; t++)
                        mma_bf16(&acc[(mt * 4 + p * 2 + t) * 4], &ah[mt * 4],
                                 &bl[p * 4 + t * 2]);  // hi*lo
#pragma unroll
                for (int mt = 0; mt < 4; mt++)
#pragma unroll
                    for (int t = 0; t < 2; t++)
                        mma_bf16(&acc[(mt * 4 + p * 2 + t) * 4], &al[mt * 4],
                                 &bh[p * 4 + t * 2]);  // lo*hi
            }
        }
    }

    const int quad = L >> 2, ql = L & 3;
    float* Cfg = Cf + (long)g * cfGrp;
    bf16* OHg = OH + (long)g * oGrp;
    bf16* OLg = OL + (long)g * oGrp;
#pragma unroll
    for (int mt = 0; mt < 4; mt++) {
        int r0 = m0 + wr * 64 + mt * 16 + quad;
#pragma unroll
        for (int nt = 0; nt < 4; nt++) {
            int lc = wc * 32 + nt * 8 + (ql << 1);
            int col = n0 + lc;
            if (col < N)
                epi_store<ACT, WF32, WB16>(&acc[(mt * 4 + nt) * 4], sBias, lc,
                                           r0, Cfg, ldcf, OHg, OLg, ldo, col);
        }
    }
}

// ---------------- SMALL GEMM: 64x64 tile, 128 thr ---------------------------
#define SSTAGE 20480
#define SSMEM  (2 * SSTAGE + 512)

__device__ __forceinline__ void stage_small(
    uint32_t sb, const bf16* Ahg, const bf16* Alg, int lda, const bf16* WHg,
    const bf16* WLg, int K, int k0, int n0, int N, int tid) {
#pragma unroll
    for (int i = 0; i < 2; i++) {
        int v = tid + (i << 7);
        int r = v >> 2, q = v & 3;
        uint32_t d = (uint32_t)(r * 80 + (q << 4));
        long ao = (long)r * lda + k0 + (q << 3);
        cpa16(sb + d, Ahg + ao, true);
        cpa16(sb + 5120 + d, Alg + ao, true);
        bool bp = (n0 + r) < N;
        long bo = bp ? ((long)r * K + k0 + (q << 3)) : 0;
        cpa16(sb + 10240 + d, WHg + bo, bp);
        cpa16(sb + 15360 + d, WLg + bo, bp);
    }
}

template <int ACT, bool WF32, bool WB16>
__global__ __launch_bounds__(128, 4)
void gemm_s(const bf16* __restrict__ Ah, const bf16* __restrict__ Al,
            long aGrp, int lda, const bf16* __restrict__ WH,
            const bf16* __restrict__ WL, long wGrp,
            const float* __restrict__ Bias, long bGrp,
            float* __restrict__ Cf, long cfGrp, int ldcf,
            bf16* __restrict__ OH, bf16* __restrict__ OL, long oGrp, int ldo,
            int N, int K) {
    extern __shared__ char smem[];
    const uint32_t sbs = smem_u32(smem);
    float* sBias = (float*)(smem + 2 * SSTAGE);

    const int tid = threadIdx.x, w = tid >> 5, L = tid & 31;
    const int wr = w >> 1, wc = w & 1;
    const int g = blockIdx.z;
    const int m0 = blockIdx.y * 64, n0 = blockIdx.x * 64;

    const bf16* Ahg = Ah + (long)g * aGrp + (long)m0 * lda;
    const bf16* Alg = Al + (long)g * aGrp + (long)m0 * lda;
    const bf16* WHg = WH + (long)g * wGrp + (long)n0 * K;
    const bf16* WLg = WL + (long)g * wGrp + (long)n0 * K;

    if (tid < 64) {
        int c = n0 + tid;
        sBias[tid] = (c < N) ? Bias[(long)g * bGrp + c] : 0.f;
    }

    float acc[32];
#pragma unroll
    for (int i = 0; i < 32; i++) acc[i] = 0.f;

    const uint32_t a_off =
        (uint32_t)((wr * 32 + (L & 7) + ((L >> 3) & 1) * 8) * 80 +
                   ((L >> 4) & 1) * 16);
    const uint32_t b_off =
        (uint32_t)((wc * 32 + (L & 7) + ((L >> 4) & 1) * 8) * 80 +
                   ((L >> 3) & 1) * 16);

    const int nch = K >> 5;
    stage_small(sbs, Ahg, Alg, lda, WHg, WLg, K, 0, n0, N, tid);
    CP_COMMIT();

    for (int ch = 0; ch < nch; ch++) {
        CP_WAIT0();
        __syncthreads();
        if (ch + 1 < nch)
            stage_small(sbs + ((ch + 1) & 1) * SSTAGE, Ahg, Alg, lda, WHg, WLg,
                        K, (ch + 1) << 5, n0, N, tid);
        CP_COMMIT();

        const uint32_t ab = sbs + (ch & 1) * SSTAGE;
        const uint32_t bb = ab + 10240;
#pragma unroll
        for (int s = 0; s < 2; s++) {
            uint32_t ah[8], al[8], bh[8], bl[8];
#pragma unroll
            for (int p = 0; p < 2; p++) {
                uint32_t bd = b_off + p * 1280 + s * 32;
                ldsm4(&bh[p * 4], bb + bd);
                ldsm4(&bl[p * 4], bb + 5120 + bd);
            }
#pragma unroll
            for (int mt = 0; mt < 2; mt++) {
                uint32_t ad = a_off + mt * 1280 + s * 32;
                ldsm4(&ah[mt * 4], ab + ad);
                ldsm4(&al[mt * 4], ab + 5120 + ad);
            }
#pragma unroll
            for (int p = 0; p < 2; p++) {
#pragma unroll
                for (int mt = 0; mt < 2; mt++)
#pragma unroll
                    for (int t = 0; t < 2; t++)
                        mma_bf16(&acc[(mt * 4 + p * 2 + t) * 4], &ah[mt * 4],
                                 &bh[p * 4 + t * 2]);
#pragma unroll
                for (int mt = 0; mt < 2; mt++)
#pragma unroll
                    for (int t = 0; t < 2; t++)
                        mma_bf16(&acc[(mt * 4 + p * 2 + t) * 4], &ah[mt * 4],
                                 &bl[p * 4 + t * 2]);
#pragma unroll
                for (int mt = 0; mt < 2; mt++)
#pragma unroll
                    for (int t = 0; t < 2; t++)
                        mma_bf16(&acc[(mt * 4 + p * 2 + t) * 4], &al[mt * 4],
                                 &bh[p * 4 + t * 2]);
            }
        }
    }

    const int quad = L >> 2, ql = L & 3;
    float* Cfg = Cf + (long)g * cfGrp;
    bf16* OHg = OH + (long)g * oGrp;
    bf16* OLg = OL + (long)g * oGrp;
#pragma unroll
    for (int mt = 0; mt < 2; mt++) {
        int r0 = m0 + wr * 32 + mt * 16 + quad;
#pragma unroll
        for (int nt = 0; nt < 4; nt++) {
            int lc = wc * 32 + nt * 8 + (ql << 1);
            int col = n0 + lc;
            if (col < N)
                epi_store<ACT, WF32, WB16>(&acc[(mt * 4 + nt) * 4], sBias, lc,
                                           r0, Cfg, ldcf, OHg, OLg, ldo, col);
        }
    }
}

// ---------------- host side -------------------------------------------------
struct GemmArgs {
    const bf16 *Ah, *Al; long aGrp; int lda;
    const bf16 *WH, *WL; long wGrp;
    const float* Bias; long bGrp;
    float* Cf; long cfGrp; int ldcf;
    bf16 *OH, *OL; long oGrp; int ldo;
    int N, K, G;
};

template <int ACT, bool WF32, bool WB16>
static void rungemm(const GemmArgs& a) {
    dim3 grid((a.N + 127) / 128, BATCH / 128, a.G);
    gemm2<ACT, WF32, WB16><<<grid, 256, SMEM_BYTES>>>(
        a.Ah, a.Al, a.aGrp, a.lda, a.WH, a.WL, a.wGrp, a.Bias, a.bGrp, a.Cf,
        a.cfGrp, a.ldcf, a.OH, a.OL, a.oGrp, a.ldo, a.N, a.K);
}
template <int ACT, bool WF32, bool WB16>
static void rungemm_s(const GemmArgs& a) {
    dim3 grid((a.N + 63) / 64, BATCH / 64, a.G);
    gemm_s<ACT, WF32, WB16><<<grid, 128, SSMEM>>>(
        a.Ah, a.Al, a.aGrp, a.lda, a.WH, a.WL, a.wGrp, a.Bias, a.bGrp, a.Cf,
        a.cfGrp, a.ldcf, a.OH, a.OL, a.oGrp, a.ldo, a.N, a.K);
}

extern "C" void kernel_launch(void* const* d_in, const int* in_sizes, int n_in,
                              void* d_out, int out_size) {
    const float* in[31];
    for (int i = 0; i < 31; i++) in[i] = (const float*)d_in[i];
    const float* state = in[0];

    float* emb = (float*)d_out;                    // [4096, 85, 128]
    float* action = emb + (long)BATCH * 85 * 128;  // [4096, 32]

    bf16 *whi, *wlo, *h1h, *h1l, *h2h, *h2l, *th, *tl, *sh, *sl;
    cudaGetSymbolAddress((void**)&whi, g_whi);
    cudaGetSymbolAddress((void**)&wlo, g_wlo);
    cudaGetSymbolAddress((void**)&h1h, g_h1h);
    cudaGetSymbolAddress((void**)&h1l, g_h1l);
    cudaGetSymbolAddress((void**)&h2h, g_h2h);
    cudaGetSymbolAddress((void**)&h2l, g_h2l);
    cudaGetSymbolAddress((void**)&th, g_th);
    cudaGetSymbolAddress((void**)&tl, g_tl);
    cudaGetSymbolAddress((void**)&sh, g_sh);
    cudaGetSymbolAddress((void**)&sl, g_sl);

    cudaFuncSetAttribute(gemm2<1, false, true>,
                         cudaFuncAttributeMaxDynamicSharedMemorySize, SMEM_BYTES);
    cudaFuncSetAttribute(gemm2<0, true, true>,
                         cudaFuncAttributeMaxDynamicSharedMemorySize, SMEM_BYTES);
    cudaFuncSetAttribute(gemm_s<1, false, true>,
                         cudaFuncAttributeMaxDynamicSharedMemorySize, SSMEM);
    cudaFuncSetAttribute(gemm_s<0, true, true>,
                         cudaFuncAttributeMaxDynamicSharedMemorySize, SSMEM);
    cudaFuncSetAttribute(gemm_s<2, true, false>,
                         cudaFuncAttributeMaxDynamicSharedMemorySize, SSMEM);

    const int o_e1 = 0, o_eh = 2097152, o_eo = 3145728;
    const int o_01 = 4194304, o_0h = 8388608, o_0o = 12582912;
    const int o_11 = 13631488, o_1h = 14680064, o_1o = 15728640;
    const int o_21 = 15990784, o_2h = 16252928, o_2o = 16515072;
    const int o_h1 = 16580608, o_hh = 16596992, o_ho = 16613376;

    PrepJobs J;
    const int srcIdx[15] = {1, 3, 5, 7, 9, 11, 13, 15, 17, 19, 21, 23, 25, 27, 29};
    const int dofs[15] = {o_e1, o_eh, o_eo, o_01, o_0h, o_0o, o_11, o_1h,
                          o_1o, o_21, o_2h, o_2o, o_h1, o_hh, o_ho};
    const int Ks[15] = {256, 128, 128, 512, 512, 512, 512, 512,
                        512, 512, 512, 512, 128, 128, 128};
    const int Ns[15] = {128, 128, 128, 512, 512, 128, 512, 512,
                        128, 512, 512, 128, 128, 128, 32};
    const int Gs[15] = {64, 64, 64, 16, 16, 16, 4, 4, 4, 1, 1, 1, 1, 1, 1};
    int base = 0;
    for (int i = 0; i < 15; i++) {
        J.src[i] = in[srcIdx[i]];
        J.dstOff[i] = dofs[i];
        J.K[i] = Ks[i];
        J.N[i] = Ns[i];
        J.tileBase[i] = base;
        base += Gs[i] * (Ks[i] >> 5) * (Ns[i] >> 5);
    }
    J.tileBase[15] = base;
    prep_all<<<base, dim3(32, 8)>>>(J, whi, wlo);              // launch 1
    cvt_split<<<1024, 256>>>(state, sh, sl, BATCH * 256 / 4);  // launch 2

    const int D = 128, CD = 512;
    GemmArgs a;

    // encoders (G=64)                                          launches 3-5
    a = {sh, sl, 0L, 256, whi + o_e1, wlo + o_e1, 128L * 256, in[2], D,
         nullptr, 0L, 0, h1h, h1l, (long)BATCH * D, D, D, 256, 64};
    rungemm<1, false, true>(a);
    a = {h1h, h1l, (long)BATCH * D, D, whi + o_eh, wlo + o_eh, 128L * 128,
         in[4], D, nullptr, 0L, 0, h2h, h2l, (long)BATCH * D, D, D, 128, 64};
    rungemm<1, false, true>(a);
    a = {h2h, h2l, (long)BATCH * D, D, whi + o_eo, wlo + o_eo, 128L * 128,
         in[6], D, emb, (long)D, LDE, th, tl, (long)D, LDE, D, 128, 64};
    rungemm<0, true, true>(a);

    // agg0 (G=16)                                   launch 6 = ncu target
    a = {th, tl, 512L, LDE, whi + o_01, wlo + o_01, 512L * 512, in[8], CD,
         nullptr, 0L, 0, h1h, h1l, (long)BATCH * CD, CD, CD, 512, 16};
    rungemm<1, false, true>(a);
    a = {h1h, h1l, (long)BATCH * CD, CD, whi + o_0h, wlo + o_0h, 512L * 512,
         in[10], CD, nullptr, 0L, 0, h2h, h2l, (long)BATCH * CD, CD, CD, 512, 16};
    rungemm<1, false, true>(a);
    a = {h2h, h2l, (long)BATCH * CD, CD, whi + o_0o, wlo + o_0o, 128L * 512,
         in[12], D, emb + 64 * 128, (long)D, LDE, th + 64 * 128, tl + 64 * 128,
         (long)D, LDE, D, 512, 16};
    rungemm<0, true, true>(a);

    // agg1 (G=4)
    a = {th + 64 * 128, tl + 64 * 128, 512L, LDE, whi + o_11, wlo + o_11,
         512L * 512, in[14], CD, nullptr, 0L, 0, h1h, h1l, (long)BATCH * CD,
         CD, CD, 512, 4};
    rungemm<1, false, true>(a);
    a = {h1h, h1l, (long)BATCH * CD, CD, whi + o_1h, wlo + o_1h, 512L * 512,
         in[16], CD, nullptr, 0L, 0, h2h, h2l, (long)BATCH * CD, CD, CD, 512, 4};
    rungemm<1, false, true>(a);
    a = {h2h, h2l, (long)BATCH * CD, CD, whi + o_1o, wlo + o_1o, 128L * 512,
         in[18], D, emb + 80 * 128, (long)D, LDE, th + 80 * 128, tl + 80 * 128,
         (long)D, LDE, D, 512, 4};
    rungemm_s<0, true, true>(a);

    // agg2 (G=1) — SMALL kernel
    a = {th + 80 * 128, tl + 80 * 128, 0L, LDE, whi + o_21, wlo + o_21, 0L,
         in[20], 0L, nullptr, 0L, 0, h1h, h1l, 0L, CD, CD, 512, 1};
    rungemm_s<1, false, true>(a);
    a = {h1h, h1l, 0L, CD, whi + o_2h, wlo + o_2h, 0L, in[22], 0L, nullptr, 0L,
         0, h2h, h2l, 0L, CD, CD, 512, 1};
    rungemm_s<1, false, true>(a);
    a = {h2h, h2l, 0L, CD, whi + o_2o, wlo + o_2o, 0L, in[24], 0L,
         emb + 84 * 128, 0L, LDE, th + 84 * 128, tl + 84 * 128, 0L, LDE, D,
         512, 1};
    rungemm_s<0, true, true>(a);

    // head (G=1) — SMALL kernel
    a = {th + 84 * 128, tl + 84 * 128, 0L, LDE, whi + o_h1, wlo + o_h1, 0L,
         in[26], 0L, nullptr, 0L, 0, h1h, h1l, 0L, D, D, 128, 1};
    rungemm_s<1, false, true>(a);
    a = {h1h, h1l, 0L, D, whi + o_hh, wlo + o_hh, 0L, in[28], 0L, nullptr, 0L,
         0, h2h, h2l, 0L, D, D, 128, 1};
    rungemm_s<1, false, true>(a);
    a = {h2h, h2l, 0L, D, whi + o_ho, wlo + o_ho, 0L, in[30], 0L, action, 0L,
         32, nullptr, nullptr, 0L, 0, 32, 128, 1};
    rungemm_s<2, true, false>(a);
}